// round 2
// baseline (speedup 1.0000x reference)
#include <cuda_runtime.h>
#include <math.h>

#define D 128
#define NMAX 50000
#define EMAX 640000
#define GRU_ROWS 16
#define DEC_ROWS 32

// ---------------- scratch (static device globals; no allocs allowed) ----------
__device__ __align__(16) float g_prev[NMAX * D];          // GRU hidden state
__device__ __align__(16) float g_hsum[NMAX * D];          // running sum of h
__device__ __align__(16) float g_hagg[NMAX * D];          // per-layer aggregation
__device__ __align__(16) float g_y0[NMAX * (D / 2)];      // decode pre-BN activations
__device__ __align__(16) float g_stats[2 * D + 2 * (D / 2)];
__device__ __align__(16) float g_WT[D * 768];              // k-major fused [W_ih | W_hh]
__device__ __align__(16) float g_WTd[D * (D / 2)];         // k-major W_dec

// ---------------- prep: zero stats + transpose weights to k-major -------------
__global__ void prep_kernel(const float* __restrict__ Wih,
                            const float* __restrict__ Whh,
                            const float* __restrict__ Wdec) {
    int i = blockIdx.x * blockDim.x + threadIdx.x;
    int stride = gridDim.x * blockDim.x;
    if (i < 2 * D + D) g_stats[i] = 0.f; // 384 entries
    for (int idx = i; idx < D * 768; idx += stride) {
        int k = idx / 768, m = idx % 768;
        g_WT[idx] = (m < 384) ? Wih[m * D + k] : Whh[(m - 384) * D + k];
    }
    for (int idx = i; idx < D * (D / 2); idx += stride) {
        int k = idx / (D / 2), j = idx % (D / 2);
        g_WTd[idx] = Wdec[j * D + k];
    }
}

// ---------------- encoder batchnorm stats (h0 = x @ W_enc^T) ------------------
__global__ void enc_stats_kernel(const float* __restrict__ x,
                                 const float* __restrict__ Wenc, int N) {
    int d = threadIdx.x; // 0..127
    float w0 = Wenc[d * 3 + 0], w1 = Wenc[d * 3 + 1], w2 = Wenc[d * 3 + 2];
    int n0 = blockIdx.x * 256;
    int lim = min(256, N - n0);
    float s = 0.f, sq = 0.f;
    for (int r = 0; r < lim; r++) {
        int n = n0 + r;
        float h = fmaf(x[n * 3 + 0], w0, fmaf(x[n * 3 + 1], w1, x[n * 3 + 2] * w2));
        s += h;
        sq += h * h;
    }
    atomicAdd(&g_stats[d], s);
    atomicAdd(&g_stats[D + d], sq);
}

// ---------------- encoder apply: h = relu(BN(h0)); prev=h; hsum=h -------------
__global__ void enc_apply_kernel(const float* __restrict__ x,
                                 const float* __restrict__ Wenc,
                                 const float* __restrict__ gamma,
                                 const float* __restrict__ beta, int N) {
    int d = threadIdx.x;
    float w0 = Wenc[d * 3 + 0], w1 = Wenc[d * 3 + 1], w2 = Wenc[d * 3 + 2];
    float invN = 1.f / (float)N;
    float mu = g_stats[d] * invN;
    float var = g_stats[D + d] * invN - mu * mu;
    float rs = rsqrtf(var + 1e-5f);
    float ga = gamma[d] * rs;
    float be = beta[d] - mu * ga;
    int n0 = blockIdx.x * 256;
    int lim = min(256, N - n0);
    for (int r = 0; r < lim; r++) {
        int n = n0 + r;
        float h = fmaf(x[n * 3 + 0], w0, fmaf(x[n * 3 + 1], w1, x[n * 3 + 2] * w2));
        float v = fmaf(h, ga, be);
        v = v > 0.f ? v : 0.f;
        g_prev[(size_t)n * D + d] = v;
        g_hsum[(size_t)n * D + d] = v;
    }
}

// ---------------- zero h_agg ---------------------------------------------------
__global__ void zero_hagg_kernel(int total4) {
    int i = blockIdx.x * blockDim.x + threadIdx.x;
    if (i < total4) reinterpret_cast<float4*>(g_hagg)[i] = make_float4(0.f, 0.f, 0.f, 0.f);
}

// ---------------- edge scatter: h_agg[dst] += norm * prev[src] ----------------
// one warp per edge, lane handles 4 floats, vector RED to L2
__global__ void scatter_kernel(const int* __restrict__ ei,
                               const float* __restrict__ norm, int E) {
    int gw = (blockIdx.x * blockDim.x + threadIdx.x) >> 5;
    int lane = threadIdx.x & 31;
    if (gw >= E) return;
    int s = ei[gw];
    int t = ei[E + gw];
    float nv = norm[gw];
    const float4* pr = reinterpret_cast<const float4*>(g_prev + (size_t)s * D);
    float4 v = pr[lane];
    v.x *= nv; v.y *= nv; v.z *= nv; v.w *= nv;
    float* dstp = g_hagg + (size_t)t * D + lane * 4;
    unsigned long long ga = (unsigned long long)__cvta_generic_to_global(dstp);
    asm volatile("red.global.add.v4.f32 [%0], {%1,%2,%3,%4};"
                 :: "l"(ga), "f"(v.x), "f"(v.y), "f"(v.z), "f"(v.w)
                 : "memory");
}

// ---------------- GRU cell + hsum accumulation ---------------------------------
__global__ void __launch_bounds__(128) gru_kernel(const float* __restrict__ bih,
                                                  const float* __restrict__ bhh, int N) {
    __shared__ float s_a[GRU_ROWS * D];
    __shared__ float s_h[GRU_ROWS * D];
    int d = threadIdx.x;
    int n0 = blockIdx.x * GRU_ROWS;

    for (int i = d; i < GRU_ROWS * D; i += 128) {
        int n = n0 + i / D;
        float av = 0.f, hv = 0.f;
        if (n < N) {
            av = g_hagg[(size_t)n0 * D + i];
            hv = g_prev[(size_t)n0 * D + i];
        }
        s_a[i] = av;
        s_h[i] = hv;
    }
    __syncthreads();

    float air[GRU_ROWS], aiz[GRU_ROWS], ain[GRU_ROWS];
    float ahr[GRU_ROWS], ahz[GRU_ROWS], ahn[GRU_ROWS];
#pragma unroll
    for (int r = 0; r < GRU_ROWS; r++) {
        air[r] = aiz[r] = ain[r] = 0.f;
        ahr[r] = ahz[r] = ahn[r] = 0.f;
    }

#pragma unroll 2
    for (int k = 0; k < D; k++) {
        const float* row = g_WT + k * 768;
        float wir = row[d];
        float wiz = row[128 + d];
        float win = row[256 + d];
        float whr = row[384 + d];
        float whz = row[512 + d];
        float whn = row[640 + d];
#pragma unroll
        for (int r = 0; r < GRU_ROWS; r++) {
            float a = s_a[r * D + k];
            float h = s_h[r * D + k];
            air[r] = fmaf(wir, a, air[r]);
            aiz[r] = fmaf(wiz, a, aiz[r]);
            ain[r] = fmaf(win, a, ain[r]);
            ahr[r] = fmaf(whr, h, ahr[r]);
            ahz[r] = fmaf(whz, h, ahz[r]);
            ahn[r] = fmaf(whn, h, ahn[r]);
        }
    }

    float bir = bih[d], biz = bih[128 + d], bin = bih[256 + d];
    float bhr = bhh[d], bhz = bhh[128 + d], bhn = bhh[256 + d];

#pragma unroll
    for (int r = 0; r < GRU_ROWS; r++) {
        int n = n0 + r;
        if (n >= N) break;
        float gr = (air[r] + bir) + (ahr[r] + bhr);
        float gz = (aiz[r] + biz) + (ahz[r] + bhz);
        float hn_ = ahn[r] + bhn;
        float in_ = ain[r] + bin;
        float rg = 1.f / (1.f + __expf(-gr));
        float zg = 1.f / (1.f + __expf(-gz));
        float ng = tanhf(fmaf(rg, hn_, in_));
        float hp = s_h[r * D + d];
        float hnew = fmaf(zg, hp - ng, ng); // (1-z)*n + z*h
        g_prev[(size_t)n * D + d] = hnew;
        g_hsum[(size_t)n * D + d] += s_a[r * D + d];
    }
}

// ---------------- decode pass 1: y0 = (hsum/6) @ W_dec^T + column stats --------
__global__ void __launch_bounds__(64) dec1_kernel(int N) {
    __shared__ float s_z[DEC_ROWS * D];
    int j = threadIdx.x; // 0..63
    int n0 = blockIdx.x * DEC_ROWS;
    const float inv6 = 1.f / 6.f;
    for (int i = j; i < DEC_ROWS * D; i += 64) {
        int n = n0 + i / D;
        s_z[i] = (n < N) ? g_hsum[(size_t)n0 * D + i] * inv6 : 0.f;
    }
    __syncthreads();

    float acc[DEC_ROWS];
#pragma unroll
    for (int r = 0; r < DEC_ROWS; r++) acc[r] = 0.f;

#pragma unroll 2
    for (int k = 0; k < D; k++) {
        float w = g_WTd[k * (D / 2) + j];
#pragma unroll
        for (int r = 0; r < DEC_ROWS; r++) acc[r] = fmaf(w, s_z[r * D + k], acc[r]);
    }

    float s = 0.f, sq = 0.f;
#pragma unroll
    for (int r = 0; r < DEC_ROWS; r++) {
        int n = n0 + r;
        if (n < N) {
            g_y0[(size_t)n * (D / 2) + j] = acc[r];
            s += acc[r];
            sq += acc[r] * acc[r];
        }
    }
    atomicAdd(&g_stats[2 * D + j], s);
    atomicAdd(&g_stats[2 * D + (D / 2) + j], sq);
}

// ---------------- decode pass 2: out = relu(BN(y0)) @ W_dec2^T -----------------
__global__ void dec2_kernel(const float* __restrict__ gamma,
                            const float* __restrict__ beta,
                            const float* __restrict__ W2,
                            float* __restrict__ out, int N) {
    int warp = (blockIdx.x * blockDim.x + threadIdx.x) >> 5;
    int lane = threadIdx.x & 31;
    if (warp >= N) return;
    float invN = 1.f / (float)N;
    float acc = 0.f;
#pragma unroll
    for (int t = 0; t < 2; t++) {
        int jj = lane + t * 32;
        float mu = g_stats[2 * D + jj] * invN;
        float var = g_stats[2 * D + (D / 2) + jj] * invN - mu * mu;
        float rs = rsqrtf(var + 1e-5f);
        float v = (g_y0[(size_t)warp * (D / 2) + jj] - mu) * rs * gamma[jj] + beta[jj];
        v = v > 0.f ? v : 0.f;
        acc = fmaf(v, W2[jj], acc);
    }
#pragma unroll
    for (int o = 16; o > 0; o >>= 1) acc += __shfl_down_sync(0xffffffffu, acc, o);
    if (lane == 0) out[warp] = acc;
}

// ---------------- launch --------------------------------------------------------
extern "C" void kernel_launch(void* const* d_in, const int* in_sizes, int n_in,
                              void* d_out, int out_size) {
    const float* x    = (const float*)d_in[0];
    const int*   ei   = (const int*)d_in[1];   // int32 (JAX x64 disabled)
    const float* norm = (const float*)d_in[2];
    const float* Wenc = (const float*)d_in[3];
    const float* beg  = (const float*)d_in[4];
    const float* beb  = (const float*)d_in[5];
    const float* Wih  = (const float*)d_in[6];
    const float* Whh  = (const float*)d_in[7];
    const float* bih  = (const float*)d_in[8];
    const float* bhh  = (const float*)d_in[9];
    const float* Wdec = (const float*)d_in[10];
    const float* bdg  = (const float*)d_in[11];
    const float* bdb  = (const float*)d_in[12];
    const float* W2   = (const float*)d_in[13];

    int N = in_sizes[0] / 3;
    int E = in_sizes[2];
    float* out = (float*)d_out;

    prep_kernel<<<128, 256>>>(Wih, Whh, Wdec);

    int nb256 = (N + 255) / 256;
    enc_stats_kernel<<<nb256, 128>>>(x, Wenc, N);
    enc_apply_kernel<<<nb256, 128>>>(x, Wenc, beg, beb, N);

    int total4 = N * D / 4;
    int zb = (total4 + 255) / 256;
    long long sthreads = (long long)E * 32;
    int sb = (int)((sthreads + 255) / 256);
    int gb = (N + GRU_ROWS - 1) / GRU_ROWS;

    for (int L = 0; L < 5; L++) {
        zero_hagg_kernel<<<zb, 256>>>(total4);
        scatter_kernel<<<sb, 256>>>(ei, norm, E);
        gru_kernel<<<gb, 128>>>(bih, bhh, N);
    }

    dec1_kernel<<<(N + DEC_ROWS - 1) / DEC_ROWS, 64>>>(N);

    long long d2threads = (long long)N * 32;
    dec2_kernel<<<(int)((d2threads + 255) / 256), 256>>>(bdg, bdb, W2, out, N);
}

// round 3
// speedup vs baseline: 1.0712x; 1.0712x over previous
#include <cuda_runtime.h>
#include <math.h>

#define D 128
#define NMAX 50000
#define GRU_ROWS 16
#define DEC_ROWS 32

// ---------------- scratch (static device globals; no allocs allowed) ----------
__device__ __align__(16) float g_prev[NMAX * D];
__device__ __align__(16) float g_hsum[NMAX * D];
__device__ __align__(16) float g_hagg[NMAX * D];
__device__ __align__(16) float g_y0[NMAX * (D / 2)];
__device__ __align__(16) float g_stats[2 * D + 2 * (D / 2)];
__device__ __align__(16) float2 g_Wp[D * 384];   // paired weights: [k][gate][d] -> {W_ih, W_hh}
__device__ __align__(16) float g_WTd[D * (D / 2)];

__device__ __forceinline__ void ffma2(unsigned long long& acc,
                                      unsigned long long a,
                                      unsigned long long b) {
    asm("fma.rn.f32x2 %0, %1, %2, %0;" : "+l"(acc) : "l"(a), "l"(b));
}
__device__ __forceinline__ float2 unpk(unsigned long long v) {
    float2 u;
    asm("mov.b64 {%0,%1}, %2;" : "=f"(u.x), "=f"(u.y) : "l"(v));
    return u;
}

// ---------------- prep: zero stats + pack weights -----------------------------
__global__ void prep_kernel(const float* __restrict__ Wih,
                            const float* __restrict__ Whh,
                            const float* __restrict__ Wdec) {
    int i = blockIdx.x * blockDim.x + threadIdx.x;
    int stride = gridDim.x * blockDim.x;
    if (i < 2 * D + D) g_stats[i] = 0.f;
    for (int idx = i; idx < D * 384; idx += stride) {
        int k = idx / 384, m = idx % 384;     // m = gate*128 + d
        g_Wp[idx] = make_float2(Wih[m * D + k], Whh[m * D + k]);
    }
    for (int idx = i; idx < D * (D / 2); idx += stride) {
        int k = idx / (D / 2), j = idx % (D / 2);
        g_WTd[idx] = Wdec[j * D + k];
    }
}

// ---------------- encoder batchnorm stats --------------------------------------
__global__ void enc_stats_kernel(const float* __restrict__ x,
                                 const float* __restrict__ Wenc, int N) {
    int d = threadIdx.x;
    float w0 = Wenc[d * 3 + 0], w1 = Wenc[d * 3 + 1], w2 = Wenc[d * 3 + 2];
    int n0 = blockIdx.x * 256;
    int lim = min(256, N - n0);
    float s = 0.f, sq = 0.f;
    for (int r = 0; r < lim; r++) {
        int n = n0 + r;
        float h = fmaf(x[n * 3 + 0], w0, fmaf(x[n * 3 + 1], w1, x[n * 3 + 2] * w2));
        s += h;
        sq += h * h;
    }
    atomicAdd(&g_stats[d], s);
    atomicAdd(&g_stats[D + d], sq);
}

// ---------------- encoder apply -------------------------------------------------
__global__ void enc_apply_kernel(const float* __restrict__ x,
                                 const float* __restrict__ Wenc,
                                 const float* __restrict__ gamma,
                                 const float* __restrict__ beta, int N) {
    int d = threadIdx.x;
    float w0 = Wenc[d * 3 + 0], w1 = Wenc[d * 3 + 1], w2 = Wenc[d * 3 + 2];
    float invN = 1.f / (float)N;
    float mu = g_stats[d] * invN;
    float var = g_stats[D + d] * invN - mu * mu;
    float rs = rsqrtf(var + 1e-5f);
    float ga = gamma[d] * rs;
    float be = beta[d] - mu * ga;
    int n0 = blockIdx.x * 256;
    int lim = min(256, N - n0);
    for (int r = 0; r < lim; r++) {
        int n = n0 + r;
        float h = fmaf(x[n * 3 + 0], w0, fmaf(x[n * 3 + 1], w1, x[n * 3 + 2] * w2));
        float v = fmaf(h, ga, be);
        v = v > 0.f ? v : 0.f;
        g_prev[(size_t)n * D + d] = v;
        g_hsum[(size_t)n * D + d] = v;
    }
}

// ---------------- edge scatter: h_agg[dst] += norm * prev[src] -----------------
__global__ void scatter_kernel(const int* __restrict__ ei,
                               const float* __restrict__ norm, int E) {
    int gw = (blockIdx.x * blockDim.x + threadIdx.x) >> 5;
    int lane = threadIdx.x & 31;
    if (gw >= E) return;
    int s = ei[gw];
    int t = ei[E + gw];
    float nv = norm[gw];
    const float4* pr = reinterpret_cast<const float4*>(g_prev + (size_t)s * D);
    float4 v = pr[lane];
    v.x *= nv; v.y *= nv; v.z *= nv; v.w *= nv;
    float* dstp = g_hagg + (size_t)t * D + lane * 4;
    unsigned long long ga = (unsigned long long)__cvta_generic_to_global(dstp);
    asm volatile("red.global.add.v4.f32 [%0], {%1,%2,%3,%4};"
                 :: "l"(ga), "f"(v.x), "f"(v.y), "f"(v.z), "f"(v.w)
                 : "memory");
}

// ---------------- GRU cell via packed f32x2 FMA ---------------------------------
// Pair = {input-gate dot, hidden-gate dot}; operand pair = {h_agg, prev_h};
// weight pair = {W_ih, W_hh}. Also zeroes g_hagg (read-then-clear) and adds hsum.
__global__ void __launch_bounds__(128) gru_kernel(const float* __restrict__ bih,
                                                  const float* __restrict__ bhh, int N) {
    __shared__ float2 s_ah[D * 17];   // [k][r], pad 17 vs 16 to break bank wrap
    int d = threadIdx.x;
    int n0 = blockIdx.x * GRU_ROWS;

#pragma unroll
    for (int j = 0; j < GRU_ROWS * D; j += 128) {
        int idx = j + d;
        int r = idx >> 7;
        int k = idx & 127;
        float a = 0.f, h = 0.f;
        if (n0 + r < N) {
            size_t gi = (size_t)n0 * D + idx;
            a = g_hagg[gi];
            h = g_prev[gi];
            g_hagg[gi] = 0.f;     // clear for next layer's scatter
        }
        s_ah[k * 17 + r] = make_float2(a, h);
    }
    __syncthreads();

    unsigned long long accr[GRU_ROWS], accz[GRU_ROWS], accn[GRU_ROWS];
#pragma unroll
    for (int r = 0; r < GRU_ROWS; r++) { accr[r] = 0ull; accz[r] = 0ull; accn[r] = 0ull; }

    const unsigned long long* Wp = reinterpret_cast<const unsigned long long*>(g_Wp);

#pragma unroll 2
    for (int k = 0; k < D; k++) {
        unsigned long long wr = Wp[k * 384 + d];
        unsigned long long wz = Wp[k * 384 + 128 + d];
        unsigned long long wn = Wp[k * 384 + 256 + d];
        const unsigned long long* row =
            reinterpret_cast<const unsigned long long*>(s_ah + k * 17);
#pragma unroll
        for (int r = 0; r < GRU_ROWS; r++) {
            unsigned long long ah = row[r];
            ffma2(accr[r], ah, wr);
            ffma2(accz[r], ah, wz);
            ffma2(accn[r], ah, wn);
        }
    }

    float bir = bih[d], biz = bih[128 + d], bin = bih[256 + d];
    float bhr = bhh[d], bhz = bhh[128 + d], bhn = bhh[256 + d];

#pragma unroll
    for (int r = 0; r < GRU_ROWS; r++) {
        int n = n0 + r;
        if (n >= N) break;
        float2 R = unpk(accr[r]);
        float2 Z = unpk(accz[r]);
        float2 Nv = unpk(accn[r]);
        float gr = (R.x + bir) + (R.y + bhr);
        float gz = (Z.x + biz) + (Z.y + bhz);
        float in_ = Nv.x + bin;
        float hn_ = Nv.y + bhn;
        float rg = 1.f / (1.f + __expf(-gr));
        float zg = 1.f / (1.f + __expf(-gz));
        float ng = tanhf(fmaf(rg, hn_, in_));
        float2 AH = s_ah[d * 17 + r];           // {a, prev_h} at (r, d)
        float hnew = fmaf(zg, AH.y - ng, ng);   // (1-z)*n + z*h
        g_prev[(size_t)n * D + d] = hnew;
        g_hsum[(size_t)n * D + d] += AH.x;
    }
}

// ---------------- decode pass 1 -------------------------------------------------
__global__ void __launch_bounds__(64) dec1_kernel(int N) {
    __shared__ float s_z[DEC_ROWS * D];
    int j = threadIdx.x;
    int n0 = blockIdx.x * DEC_ROWS;
    const float inv6 = 1.f / 6.f;
    for (int i = j; i < DEC_ROWS * D; i += 64) {
        int n = n0 + i / D;
        s_z[i] = (n < N) ? g_hsum[(size_t)n0 * D + i] * inv6 : 0.f;
    }
    __syncthreads();

    float acc[DEC_ROWS];
#pragma unroll
    for (int r = 0; r < DEC_ROWS; r++) acc[r] = 0.f;

#pragma unroll 2
    for (int k = 0; k < D; k++) {
        float w = g_WTd[k * (D / 2) + j];
#pragma unroll
        for (int r = 0; r < DEC_ROWS; r++) acc[r] = fmaf(w, s_z[r * D + k], acc[r]);
    }

    float s = 0.f, sq = 0.f;
#pragma unroll
    for (int r = 0; r < DEC_ROWS; r++) {
        int n = n0 + r;
        if (n < N) {
            g_y0[(size_t)n * (D / 2) + j] = acc[r];
            s += acc[r];
            sq += acc[r] * acc[r];
        }
    }
    atomicAdd(&g_stats[2 * D + j], s);
    atomicAdd(&g_stats[2 * D + (D / 2) + j], sq);
}

// ---------------- decode pass 2 -------------------------------------------------
__global__ void dec2_kernel(const float* __restrict__ gamma,
                            const float* __restrict__ beta,
                            const float* __restrict__ W2,
                            float* __restrict__ out, int N) {
    int warp = (blockIdx.x * blockDim.x + threadIdx.x) >> 5;
    int lane = threadIdx.x & 31;
    if (warp >= N) return;
    float invN = 1.f / (float)N;
    float acc = 0.f;
#pragma unroll
    for (int t = 0; t < 2; t++) {
        int jj = lane + t * 32;
        float mu = g_stats[2 * D + jj] * invN;
        float var = g_stats[2 * D + (D / 2) + jj] * invN - mu * mu;
        float rs = rsqrtf(var + 1e-5f);
        float v = (g_y0[(size_t)warp * (D / 2) + jj] - mu) * rs * gamma[jj] + beta[jj];
        v = v > 0.f ? v : 0.f;
        acc = fmaf(v, W2[jj], acc);
    }
#pragma unroll
    for (int o = 16; o > 0; o >>= 1) acc += __shfl_down_sync(0xffffffffu, acc, o);
    if (lane == 0) out[warp] = acc;
}

// ---------------- launch --------------------------------------------------------
extern "C" void kernel_launch(void* const* d_in, const int* in_sizes, int n_in,
                              void* d_out, int out_size) {
    const float* x    = (const float*)d_in[0];
    const int*   ei   = (const int*)d_in[1];
    const float* norm = (const float*)d_in[2];
    const float* Wenc = (const float*)d_in[3];
    const float* beg  = (const float*)d_in[4];
    const float* beb  = (const float*)d_in[5];
    const float* Wih  = (const float*)d_in[6];
    const float* Whh  = (const float*)d_in[7];
    const float* bih  = (const float*)d_in[8];
    const float* bhh  = (const float*)d_in[9];
    const float* Wdec = (const float*)d_in[10];
    const float* bdg  = (const float*)d_in[11];
    const float* bdb  = (const float*)d_in[12];
    const float* W2   = (const float*)d_in[13];

    int N = in_sizes[0] / 3;
    int E = in_sizes[2];
    float* out = (float*)d_out;

    prep_kernel<<<128, 256>>>(Wih, Whh, Wdec);

    int nb256 = (N + 255) / 256;
    enc_stats_kernel<<<nb256, 128>>>(x, Wenc, N);
    enc_apply_kernel<<<nb256, 128>>>(x, Wenc, beg, beb, N);

    long long sthreads = (long long)E * 32;
    int sb = (int)((sthreads + 255) / 256);
    int gb = (N + GRU_ROWS - 1) / GRU_ROWS;

    for (int L = 0; L < 5; L++) {
        scatter_kernel<<<sb, 256>>>(ei, norm, E);
        gru_kernel<<<gb, 128>>>(bih, bhh, N);
    }

    dec1_kernel<<<(N + DEC_ROWS - 1) / DEC_ROWS, 64>>>(N);

    long long d2threads = (long long)N * 32;
    dec2_kernel<<<(int)((d2threads + 255) / 256), 256>>>(bdg, bdb, W2, out, N);
}

// round 5
// speedup vs baseline: 1.2549x; 1.1715x over previous
#include <cuda_runtime.h>
#include <cuda_bf16.h>
#include <math.h>

#define D 128
#define NMAX 50000
#define DEC_ROWS 32

// ---------------- scratch globals ------------------------------------------------
__device__ __align__(16) float g_prev[NMAX * D];
__device__ __align__(16) float g_hsum[NMAX * D];
__device__ __align__(16) float g_hagg[NMAX * D];
__device__ __align__(16) float g_y0[NMAX * (D / 2)];
__device__ __align__(16) float g_stats[2 * D + 2 * (D / 2)];
__device__ __align__(16) float g_WTd[D * (D / 2)];
__device__ __align__(16) float g_bias[512];      // [0,256) r,z combined; [256,384) b_in; [384,512) b_hn
// B fragments: [mat(6: src*3+gate)][split(2)][ntile(16)][kstep(8)][lane(32)] -> uint2 {b0,b1}
__device__ __align__(16) uint2 g_Bfrag[12 * 4096];

__device__ __forceinline__ unsigned pack_hi_lo(float x0, float x1, unsigned& lop) {
    __nv_bfloat16 h0 = __float2bfloat16(x0), h1 = __float2bfloat16(x1);
    float l0 = x0 - __bfloat162float(h0), l1 = x1 - __bfloat162float(h1);
    __nv_bfloat16 g0 = __float2bfloat16(l0), g1 = __float2bfloat16(l1);
    lop = ((unsigned)__bfloat16_as_ushort(g1) << 16) | __bfloat16_as_ushort(g0);
    return ((unsigned)__bfloat16_as_ushort(h1) << 16) | __bfloat16_as_ushort(h0);
}

__device__ __forceinline__ void mma16816(float* c, const unsigned* a, unsigned b0, unsigned b1) {
    asm("mma.sync.aligned.m16n8k16.row.col.f32.bf16.bf16.f32 "
        "{%0,%1,%2,%3}, {%4,%5,%6,%7}, {%8,%9}, {%0,%1,%2,%3};"
        : "+f"(c[0]), "+f"(c[1]), "+f"(c[2]), "+f"(c[3])
        : "r"(a[0]), "r"(a[1]), "r"(a[2]), "r"(a[3]), "r"(b0), "r"(b1));
}

// ---------------- prep: stats, biases, dec weights, B fragments ------------------
__global__ void prep_kernel(const float* __restrict__ Wih, const float* __restrict__ Whh,
                            const float* __restrict__ bih, const float* __restrict__ bhh,
                            const float* __restrict__ Wdec) {
    int i = blockIdx.x * blockDim.x + threadIdx.x;
    int stride = gridDim.x * blockDim.x;
    if (i < 384) g_stats[i] = 0.f;
    if (i < 256) g_bias[i] = bih[i] + bhh[i];
    else if (i < 384) g_bias[i] = bih[i];
    if (i >= 384 && i < 512) g_bias[i] = bhh[i - 128];
    for (int idx = i; idx < D * (D / 2); idx += stride) {
        int k = idx / (D / 2), j = idx % (D / 2);
        g_WTd[idx] = Wdec[j * D + k];
    }
    // B fragments in exact m16n8k16 col-major per-lane order
    for (int f = i; f < 12 * 4096; f += stride) {
        int lane = f & 31;
        int ks = (f >> 5) & 7;
        int nt = (f >> 8) & 15;
        int ms = f >> 12;            // 0..11
        int mat = ms >> 1, split = ms & 1;
        int src = mat / 3, gate = mat % 3;
        int gg = lane >> 2, tg = lane & 3;
        int n_local = nt * 8 + gg;
        int k0 = ks * 16 + tg * 2;
        const float* W = src ? Whh : Wih;
        const float* row = W + (size_t)(gate * 128 + n_local) * D;
        float v00 = row[k0], v01 = row[k0 + 1], v10 = row[k0 + 8], v11 = row[k0 + 9];
        unsigned w0, w1;
        if (split == 0) {
            w0 = ((unsigned)__bfloat16_as_ushort(__float2bfloat16(v01)) << 16) |
                 __bfloat16_as_ushort(__float2bfloat16(v00));
            w1 = ((unsigned)__bfloat16_as_ushort(__float2bfloat16(v11)) << 16) |
                 __bfloat16_as_ushort(__float2bfloat16(v10));
        } else {
            float l00 = v00 - __bfloat162float(__float2bfloat16(v00));
            float l01 = v01 - __bfloat162float(__float2bfloat16(v01));
            float l10 = v10 - __bfloat162float(__float2bfloat16(v10));
            float l11 = v11 - __bfloat162float(__float2bfloat16(v11));
            w0 = ((unsigned)__bfloat16_as_ushort(__float2bfloat16(l01)) << 16) |
                 __bfloat16_as_ushort(__float2bfloat16(l00));
            w1 = ((unsigned)__bfloat16_as_ushort(__float2bfloat16(l11)) << 16) |
                 __bfloat16_as_ushort(__float2bfloat16(l10));
        }
        g_Bfrag[f] = make_uint2(w0, w1);
    }
}

// ---------------- encoder --------------------------------------------------------
__global__ void enc_stats_kernel(const float* __restrict__ x, const float* __restrict__ Wenc, int N) {
    int d = threadIdx.x;
    float w0 = Wenc[d * 3], w1 = Wenc[d * 3 + 1], w2 = Wenc[d * 3 + 2];
    int n0 = blockIdx.x * 256, lim = min(256, N - n0);
    float s = 0.f, sq = 0.f;
    for (int r = 0; r < lim; r++) {
        int n = n0 + r;
        float h = fmaf(x[n * 3], w0, fmaf(x[n * 3 + 1], w1, x[n * 3 + 2] * w2));
        s += h; sq += h * h;
    }
    atomicAdd(&g_stats[d], s);
    atomicAdd(&g_stats[D + d], sq);
}
__global__ void enc_apply_kernel(const float* __restrict__ x, const float* __restrict__ Wenc,
                                 const float* __restrict__ gamma, const float* __restrict__ beta, int N) {
    int d = threadIdx.x;
    float w0 = Wenc[d * 3], w1 = Wenc[d * 3 + 1], w2 = Wenc[d * 3 + 2];
    float invN = 1.f / (float)N;
    float mu = g_stats[d] * invN;
    float var = g_stats[D + d] * invN - mu * mu;
    float rs = rsqrtf(var + 1e-5f);
    float ga = gamma[d] * rs, be = beta[d] - mu * ga;
    int n0 = blockIdx.x * 256, lim = min(256, N - n0);
    for (int r = 0; r < lim; r++) {
        int n = n0 + r;
        float h = fmaf(x[n * 3], w0, fmaf(x[n * 3 + 1], w1, x[n * 3 + 2] * w2));
        float v = fmaf(h, ga, be);
        v = v > 0.f ? v : 0.f;
        g_prev[(size_t)n * D + d] = v;
        g_hsum[(size_t)n * D + d] = v;
    }
}

// ---------------- edge scatter -----------------------------------------------------
__global__ void scatter_kernel(const int* __restrict__ ei, const float* __restrict__ norm, int E) {
    int gw = (blockIdx.x * blockDim.x + threadIdx.x) >> 5;
    int lane = threadIdx.x & 31;
    if (gw >= E) return;
    int s = ei[gw], t = ei[E + gw];
    float nv = norm[gw];
    float4 v = reinterpret_cast<const float4*>(g_prev + (size_t)s * D)[lane];
    v.x *= nv; v.y *= nv; v.z *= nv; v.w *= nv;
    unsigned long long ga = (unsigned long long)__cvta_generic_to_global(g_hagg + (size_t)t * D + lane * 4);
    asm volatile("red.global.add.v4.f32 [%0], {%1,%2,%3,%4};"
                 :: "l"(ga), "f"(v.x), "f"(v.y), "f"(v.z), "f"(v.w) : "memory");
}

// ---------------- GRU via warp-level bf16x3 mma.sync ------------------------------
// smem: 4 A buffers [half(2)][split(2)]: 128 rows x 68-word pitch (words) + 512 bias floats
#define PITCH 68
#define ABUF  (128 * PITCH)             // 8704 words per buffer
#define GRU_SMEM (4 * ABUF * 4 + 512 * 4)   // 139264 + 2048 = 141312 B

__global__ void __launch_bounds__(128, 1) gru_kernel(int N) {
    extern __shared__ unsigned char smraw[];
    unsigned* sA = (unsigned*)smraw;
    float* sbias = (float*)(smraw + 4 * ABUF * 4);
    int tid = threadIdx.x;
    int n0 = blockIdx.x * 128;

#pragma unroll
    for (int t = 0; t < 4; t++) sbias[t * 128 + tid] = g_bias[t * 128 + tid];

    // conversion phase: fp32 -> bf16 hi/lo into smem; also hsum += hagg; hagg = 0
    {
        int r = n0 + tid;
        bool val = r < N;
        const float2* pa = (const float2*)(g_hagg + (size_t)r * D);
        const float2* ph = (const float2*)(g_prev + (size_t)r * D);
        float2* ps = (float2*)(g_hsum + (size_t)r * D);
        float2* pz = (float2*)(g_hagg + (size_t)r * D);
        unsigned base = tid * PITCH;
#pragma unroll 4
        for (int kw = 0; kw < 64; kw++) {
            float2 a = val ? pa[kw] : make_float2(0.f, 0.f);
            float2 h = val ? ph[kw] : make_float2(0.f, 0.f);
            unsigned lo, hi;
            hi = pack_hi_lo(a.x, a.y, lo);
            sA[base + kw] = hi;
            sA[ABUF + base + kw] = lo;
            hi = pack_hi_lo(h.x, h.y, lo);
            sA[2 * ABUF + base + kw] = hi;
            sA[3 * ABUF + base + kw] = lo;
            if (val) {
                float2 s = ps[kw];
                ps[kw] = make_float2(s.x + a.x, s.y + a.y);
                pz[kw] = make_float2(0.f, 0.f);
            }
        }
    }
    __syncthreads();

    int lane = tid & 31, wid = tid >> 5;
    int gg = lane >> 2, tg = lane & 3;
    int m0 = wid * 32;
    const uint2* Bf = (const uint2*)g_Bfrag;

#pragma unroll 1
    for (int pass = 0; pass < 4; pass++) {
        float aR[4][8], aZ[4][8], aN[4][8], aH[4][8];
#pragma unroll
        for (int nt = 0; nt < 4; nt++)
#pragma unroll
            for (int q = 0; q < 8; q++) { aR[nt][q] = 0.f; aZ[nt][q] = 0.f; aN[nt][q] = 0.f; aH[nt][q] = 0.f; }

#pragma unroll
        for (int hf = 0; hf < 2; hf++) {
            int bh_ = (hf * 2) * ABUF;
            int bl_ = (hf * 2 + 1) * ABUF;
#pragma unroll 2
            for (int ks = 0; ks < 8; ks++) {
                int kw = ks * 8 + tg;
                unsigned Ah[8], Al[8];
                int r0 = m0 + gg;
#pragma unroll
                for (int mt = 0; mt < 2; mt++) {
                    int rr = r0 + mt * 16;
                    Ah[mt * 4 + 0] = sA[bh_ + rr * PITCH + kw];
                    Ah[mt * 4 + 1] = sA[bh_ + (rr + 8) * PITCH + kw];
                    Ah[mt * 4 + 2] = sA[bh_ + rr * PITCH + kw + 4];
                    Ah[mt * 4 + 3] = sA[bh_ + (rr + 8) * PITCH + kw + 4];
                    Al[mt * 4 + 0] = sA[bl_ + rr * PITCH + kw];
                    Al[mt * 4 + 1] = sA[bl_ + (rr + 8) * PITCH + kw];
                    Al[mt * 4 + 2] = sA[bl_ + rr * PITCH + kw + 4];
                    Al[mt * 4 + 3] = sA[bl_ + (rr + 8) * PITCH + kw + 4];
                }
#pragma unroll
                for (int gate = 0; gate < 3; gate++) {
                    int mat = hf * 3 + gate;
                    int bidx_h = (mat * 2 + 0) * 4096 + (pass * 4) * 256 + ks * 32 + lane;
                    int bidx_l = (mat * 2 + 1) * 4096 + (pass * 4) * 256 + ks * 32 + lane;
                    float (*ACC)[8] = (gate == 0) ? aR : (gate == 1) ? aZ : (hf ? aH : aN);
#pragma unroll
                    for (int nt = 0; nt < 4; nt++) {
                        uint2 bh = Bf[bidx_h + nt * 256];
                        uint2 bl = Bf[bidx_l + nt * 256];
                        mma16816(ACC[nt], Ah, bh.x, bh.y);
                        mma16816(ACC[nt], Ah, bl.x, bl.y);
                        mma16816(ACC[nt], Al, bh.x, bh.y);
                        mma16816(ACC[nt] + 4, Ah + 4, bh.x, bh.y);
                        mma16816(ACC[nt] + 4, Ah + 4, bl.x, bl.y);
                        mma16816(ACC[nt] + 4, Al + 4, bh.x, bh.y);
                    }
                }
            }
        }

        // epilogue for this pass's 32 columns
#pragma unroll
        for (int nt = 0; nt < 4; nt++) {
#pragma unroll
            for (int mt = 0; mt < 2; mt++) {
#pragma unroll
                for (int rh = 0; rh < 2; rh++) {
                    int rloc = m0 + mt * 16 + rh * 8 + gg;
                    int row = n0 + rloc;
                    if (row < N) {
                        int col = pass * 32 + nt * 8 + tg * 2;
                        int i0 = mt * 4 + rh * 2;
                        float rv0 = aR[nt][i0]     + sbias[col];
                        float rv1 = aR[nt][i0 + 1] + sbias[col + 1];
                        float zv0 = aZ[nt][i0]     + sbias[128 + col];
                        float zv1 = aZ[nt][i0 + 1] + sbias[128 + col + 1];
                        float in0 = aN[nt][i0]     + sbias[256 + col];
                        float in1 = aN[nt][i0 + 1] + sbias[256 + col + 1];
                        float hn0 = aH[nt][i0]     + sbias[384 + col];
                        float hn1 = aH[nt][i0 + 1] + sbias[384 + col + 1];
                        // reconstruct prev from smem bf16 hi+lo
                        int cw = col >> 1;
                        unsigned wh = sA[2 * ABUF + rloc * PITCH + cw];
                        unsigned wl = sA[3 * ABUF + rloc * PITCH + cw];
                        float2 fh = __bfloat1622float2(*(__nv_bfloat162*)&wh);
                        float2 fl = __bfloat1622float2(*(__nv_bfloat162*)&wl);
                        float hp0 = fh.x + fl.x, hp1 = fh.y + fl.y;
                        float rg0 = 1.f / (1.f + __expf(-rv0));
                        float rg1 = 1.f / (1.f + __expf(-rv1));
                        float zg0 = 1.f / (1.f + __expf(-zv0));
                        float zg1 = 1.f / (1.f + __expf(-zv1));
                        float ng0 = tanhf(fmaf(rg0, hn0, in0));
                        float ng1 = tanhf(fmaf(rg1, hn1, in1));
                        float o0 = fmaf(zg0, hp0 - ng0, ng0);
                        float o1 = fmaf(zg1, hp1 - ng1, ng1);
                        *(float2*)(g_prev + (size_t)row * D + col) = make_float2(o0, o1);
                    }
                }
            }
        }
    }
}

// ---------------- decode -----------------------------------------------------------
__global__ void __launch_bounds__(64) dec1_kernel(int N) {
    __shared__ float s_z[DEC_ROWS * D];
    int j = threadIdx.x;
    int n0 = blockIdx.x * DEC_ROWS;
    const float inv6 = 1.f / 6.f;
    for (int i = j; i < DEC_ROWS * D; i += 64) {
        int n = n0 + i / D;
        s_z[i] = (n < N) ? g_hsum[(size_t)n0 * D + i] * inv6 : 0.f;
    }
    __syncthreads();
    float acc[DEC_ROWS];
#pragma unroll
    for (int r = 0; r < DEC_ROWS; r++) acc[r] = 0.f;
#pragma unroll 2
    for (int k = 0; k < D; k++) {
        float w = g_WTd[k * (D / 2) + j];
#pragma unroll
        for (int r = 0; r < DEC_ROWS; r++) acc[r] = fmaf(w, s_z[r * D + k], acc[r]);
    }
    float s = 0.f, sq = 0.f;
#pragma unroll
    for (int r = 0; r < DEC_ROWS; r++) {
        int n = n0 + r;
        if (n < N) {
            g_y0[(size_t)n * (D / 2) + j] = acc[r];
            s += acc[r]; sq += acc[r] * acc[r];
        }
    }
    atomicAdd(&g_stats[2 * D + j], s);
    atomicAdd(&g_stats[2 * D + (D / 2) + j], sq);
}

__global__ void dec2_kernel(const float* __restrict__ gamma, const float* __restrict__ beta,
                            const float* __restrict__ W2, float* __restrict__ out, int N) {
    int warp = (blockIdx.x * blockDim.x + threadIdx.x) >> 5;
    int lane = threadIdx.x & 31;
    if (warp >= N) return;
    float invN = 1.f / (float)N;
    float acc = 0.f;
#pragma unroll
    for (int t = 0; t < 2; t++) {
        int jj = lane + t * 32;
        float mu = g_stats[2 * D + jj] * invN;
        float var = g_stats[2 * D + (D / 2) + jj] * invN - mu * mu;
        float rs = rsqrtf(var + 1e-5f);
        float v = (g_y0[(size_t)warp * (D / 2) + jj] - mu) * rs * gamma[jj] + beta[jj];
        v = v > 0.f ? v : 0.f;
        acc = fmaf(v, W2[jj], acc);
    }
#pragma unroll
    for (int o = 16; o > 0; o >>= 1) acc += __shfl_down_sync(0xffffffffu, acc, o);
    if (lane == 0) out[warp] = acc;
}

// ---------------- launch ------------------------------------------------------------
extern "C" void kernel_launch(void* const* d_in, const int* in_sizes, int n_in,
                              void* d_out, int out_size) {
    const float* x    = (const float*)d_in[0];
    const int*   ei   = (const int*)d_in[1];
    const float* norm = (const float*)d_in[2];
    const float* Wenc = (const float*)d_in[3];
    const float* beg  = (const float*)d_in[4];
    const float* beb  = (const float*)d_in[5];
    const float* Wih  = (const float*)d_in[6];
    const float* Whh  = (const float*)d_in[7];
    const float* bih  = (const float*)d_in[8];
    const float* bhh  = (const float*)d_in[9];
    const float* Wdec = (const float*)d_in[10];
    const float* bdg  = (const float*)d_in[11];
    const float* bdb  = (const float*)d_in[12];
    const float* W2   = (const float*)d_in[13];

    int N = in_sizes[0] / 3;
    int E = in_sizes[2];
    float* out = (float*)d_out;

    cudaFuncSetAttribute(gru_kernel, cudaFuncAttributeMaxDynamicSharedMemorySize, GRU_SMEM);

    prep_kernel<<<192, 256>>>(Wih, Whh, bih, bhh, Wdec);

    int nb256 = (N + 255) / 256;
    enc_stats_kernel<<<nb256, 128>>>(x, Wenc, N);
    enc_apply_kernel<<<nb256, 128>>>(x, Wenc, beg, beb, N);

    long long sthreads = (long long)E * 32;
    int sb = (int)((sthreads + 255) / 256);
    int gb = (N + 127) / 128;

    for (int L = 0; L < 5; L++) {
        scatter_kernel<<<sb, 256>>>(ei, norm, E);
        gru_kernel<<<gb, 128, GRU_SMEM>>>(N);
    }

    dec1_kernel<<<(N + DEC_ROWS - 1) / DEC_ROWS, 64>>>(N);

    long long d2threads = (long long)N * 32;
    dec2_kernel<<<(int)((d2threads + 255) / 256), 256>>>(bdg, bdb, W2, out, N);
}

// round 6
// speedup vs baseline: 1.7112x; 1.3636x over previous
#include <cuda_runtime.h>
#include <cuda_bf16.h>
#include <math.h>

#define D 128
#define NMAX 50000
#define DEC_ROWS 32

// ---------------- scratch globals ------------------------------------------------
__device__ __align__(16) float g_prev[NMAX * D];
__device__ __align__(16) float g_hsum[NMAX * D];
__device__ __align__(16) float g_hagg[NMAX * D];
__device__ __align__(16) float g_y0[NMAX * (D / 2)];
__device__ __align__(16) float g_stats[2 * D + 2 * (D / 2)];
__device__ __align__(16) float g_WTd[D * (D / 2)];
__device__ __align__(16) float g_bias[512];  // [0,256) r,z combined; [256,384) b_in; [384,512) b_hn
// B fragments: [mat(6: hf*3+gate)][ntile_abs(16)][kstep(8)][lane(32)] -> uint4 {hi.b0,hi.b1,lo.b0,lo.b1}
__device__ __align__(16) uint4 g_Bfrag[6 * 4096];

__device__ __forceinline__ unsigned pack_hi_lo(float x0, float x1, unsigned& lop) {
    __nv_bfloat16 h0 = __float2bfloat16(x0), h1 = __float2bfloat16(x1);
    float l0 = x0 - __bfloat162float(h0), l1 = x1 - __bfloat162float(h1);
    __nv_bfloat16 g0 = __float2bfloat16(l0), g1 = __float2bfloat16(l1);
    lop = ((unsigned)__bfloat16_as_ushort(g1) << 16) | __bfloat16_as_ushort(g0);
    return ((unsigned)__bfloat16_as_ushort(h1) << 16) | __bfloat16_as_ushort(h0);
}

__device__ __forceinline__ void mma16816(float* c, const unsigned* a, unsigned b0, unsigned b1) {
    asm("mma.sync.aligned.m16n8k16.row.col.f32.bf16.bf16.f32 "
        "{%0,%1,%2,%3}, {%4,%5,%6,%7}, {%8,%9}, {%0,%1,%2,%3};"
        : "+f"(c[0]), "+f"(c[1]), "+f"(c[2]), "+f"(c[3])
        : "r"(a[0]), "r"(a[1]), "r"(a[2]), "r"(a[3]), "r"(b0), "r"(b1));
}

// ---------------- prep ------------------------------------------------------------
__global__ void prep_kernel(const float* __restrict__ Wih, const float* __restrict__ Whh,
                            const float* __restrict__ bih, const float* __restrict__ bhh,
                            const float* __restrict__ Wdec) {
    int i = blockIdx.x * blockDim.x + threadIdx.x;
    int stride = gridDim.x * blockDim.x;
    if (i < 384) g_stats[i] = 0.f;
    if (i < 256) g_bias[i] = bih[i] + bhh[i];
    else if (i < 384) g_bias[i] = bih[i];
    if (i >= 384 && i < 512) g_bias[i] = bhh[i - 128];
    for (int idx = i; idx < D * (D / 2); idx += stride) {
        int k = idx / (D / 2), j = idx % (D / 2);
        g_WTd[idx] = Wdec[j * D + k];
    }
    // B fragments: mat = hf*3+gate (hf: 0=W_ih, 1=W_hh)
    for (int f = i; f < 6 * 4096; f += stride) {
        int lane = f & 31;
        int ks = (f >> 5) & 7;
        int nt = (f >> 8) & 15;
        int mat = f >> 12;              // 0..5
        int hf = mat / 3, gate = mat % 3;
        int gg = lane >> 2, tg = lane & 3;
        int n_local = nt * 8 + gg;
        int k0 = ks * 16 + tg * 2;
        const float* W = hf ? Whh : Wih;
        const float* row = W + (size_t)(gate * 128 + n_local) * D;
        float v00 = row[k0], v01 = row[k0 + 1], v10 = row[k0 + 8], v11 = row[k0 + 9];
        unsigned h0, h1, l0, l1;
        {
            __nv_bfloat16 a = __float2bfloat16(v00), b = __float2bfloat16(v01);
            h0 = ((unsigned)__bfloat16_as_ushort(b) << 16) | __bfloat16_as_ushort(a);
            __nv_bfloat16 la = __float2bfloat16(v00 - __bfloat162float(a));
            __nv_bfloat16 lb = __float2bfloat16(v01 - __bfloat162float(b));
            l0 = ((unsigned)__bfloat16_as_ushort(lb) << 16) | __bfloat16_as_ushort(la);
        }
        {
            __nv_bfloat16 a = __float2bfloat16(v10), b = __float2bfloat16(v11);
            h1 = ((unsigned)__bfloat16_as_ushort(b) << 16) | __bfloat16_as_ushort(a);
            __nv_bfloat16 la = __float2bfloat16(v10 - __bfloat162float(a));
            __nv_bfloat16 lb = __float2bfloat16(v11 - __bfloat162float(b));
            l1 = ((unsigned)__bfloat16_as_ushort(lb) << 16) | __bfloat16_as_ushort(la);
        }
        g_Bfrag[f] = make_uint4(h0, h1, l0, l1);
    }
}

// ---------------- encoder ----------------------------------------------------------
__global__ void enc_stats_kernel(const float* __restrict__ x, const float* __restrict__ Wenc, int N) {
    int d = threadIdx.x;
    float w0 = Wenc[d * 3], w1 = Wenc[d * 3 + 1], w2 = Wenc[d * 3 + 2];
    int n0 = blockIdx.x * 256, lim = min(256, N - n0);
    float s = 0.f, sq = 0.f;
    for (int r = 0; r < lim; r++) {
        int n = n0 + r;
        float h = fmaf(x[n * 3], w0, fmaf(x[n * 3 + 1], w1, x[n * 3 + 2] * w2));
        s += h; sq += h * h;
    }
    atomicAdd(&g_stats[d], s);
    atomicAdd(&g_stats[D + d], sq);
}
__global__ void enc_apply_kernel(const float* __restrict__ x, const float* __restrict__ Wenc,
                                 const float* __restrict__ gamma, const float* __restrict__ beta, int N) {
    int d = threadIdx.x;
    float w0 = Wenc[d * 3], w1 = Wenc[d * 3 + 1], w2 = Wenc[d * 3 + 2];
    float invN = 1.f / (float)N;
    float mu = g_stats[d] * invN;
    float var = g_stats[D + d] * invN - mu * mu;
    float rs = rsqrtf(var + 1e-5f);
    float ga = gamma[d] * rs, be = beta[d] - mu * ga;
    int n0 = blockIdx.x * 256, lim = min(256, N - n0);
    for (int r = 0; r < lim; r++) {
        int n = n0 + r;
        float h = fmaf(x[n * 3], w0, fmaf(x[n * 3 + 1], w1, x[n * 3 + 2] * w2));
        float v = fmaf(h, ga, be);
        v = v > 0.f ? v : 0.f;
        g_prev[(size_t)n * D + d] = v;
        g_hsum[(size_t)n * D + d] = v;
    }
}

// ---------------- edge scatter -------------------------------------------------------
__global__ void scatter_kernel(const int* __restrict__ ei, const float* __restrict__ norm, int E) {
    int gw = (blockIdx.x * blockDim.x + threadIdx.x) >> 5;
    int lane = threadIdx.x & 31;
    if (gw >= E) return;
    int s = ei[gw], t = ei[E + gw];
    float nv = norm[gw];
    float4 v = reinterpret_cast<const float4*>(g_prev + (size_t)s * D)[lane];
    v.x *= nv; v.y *= nv; v.z *= nv; v.w *= nv;
    unsigned long long ga = (unsigned long long)__cvta_generic_to_global(g_hagg + (size_t)t * D + lane * 4);
    asm volatile("red.global.add.v4.f32 [%0], {%1,%2,%3,%4};"
                 :: "l"(ga), "f"(v.x), "f"(v.y), "f"(v.z), "f"(v.w) : "memory");
}

// ---------------- GRU: warp-level bf16x3 mma.sync, 8 warps -----------------------------
#define PITCH 68
#define ABUF  (128 * PITCH)                 // words per A buffer
#define GRU_SMEM (4 * ABUF * 4 + 512 * 4)   // 4 bufs + biases = 141312 B

__global__ void __launch_bounds__(256, 1) gru_kernel(int N) {
    extern __shared__ unsigned char smraw[];
    unsigned* sA = (unsigned*)smraw;
    float* sbias = (float*)(smraw + 4 * ABUF * 4);
    int tid = threadIdx.x;
    int n0 = blockIdx.x * 128;

#pragma unroll
    for (int t = 0; t < 2; t++) sbias[t * 256 + tid] = g_bias[t * 256 + tid];

    // conversion: fp32 -> bf16 hi/lo into smem; hsum += hagg; hagg = 0.
    // 2 threads per row; thread half h handles odd/even words (bank- & coalesce-friendly)
    {
        int r = n0 + (tid >> 1);
        int h = tid & 1;
        bool val = r < N;
        const float2* pa = (const float2*)(g_hagg + (size_t)r * D);
        const float2* ph = (const float2*)(g_prev + (size_t)r * D);
        float2* ps = (float2*)(g_hsum + (size_t)r * D);
        float2* pz = (float2*)(g_hagg + (size_t)r * D);
        unsigned base = (tid >> 1) * PITCH;
#pragma unroll 4
        for (int j = 0; j < 32; j++) {
            int kw = 2 * j + h;
            float2 a = val ? pa[kw] : make_float2(0.f, 0.f);
            float2 hh = val ? ph[kw] : make_float2(0.f, 0.f);
            unsigned lo, hi;
            hi = pack_hi_lo(a.x, a.y, lo);
            sA[base + kw] = hi;
            sA[ABUF + base + kw] = lo;
            hi = pack_hi_lo(hh.x, hh.y, lo);
            sA[2 * ABUF + base + kw] = hi;
            sA[3 * ABUF + base + kw] = lo;
            if (val) {
                float2 s = ps[kw];
                ps[kw] = make_float2(s.x + a.x, s.y + a.y);
                pz[kw] = make_float2(0.f, 0.f);
            }
        }
    }
    __syncthreads();

    int lane = tid & 31, wid = tid >> 5;
    int gg = lane >> 2, tg = lane & 3;
    int m0 = wid * 16;                         // 16 rows per warp
    const uint4* Bf = g_Bfrag;

#pragma unroll 1
    for (int pass = 0; pass < 4; pass++) {
        float aR[4][4], aZ[4][4], aN[4][4], aH[4][4];
#pragma unroll
        for (int nt = 0; nt < 4; nt++)
#pragma unroll
            for (int q = 0; q < 4; q++) { aR[nt][q] = 0.f; aZ[nt][q] = 0.f; aN[nt][q] = 0.f; aH[nt][q] = 0.f; }

#pragma unroll
        for (int hf = 0; hf < 2; hf++) {
            __syncthreads();  // keep all 8 warps converged on the same B stream (L1 reuse)
            int bh_ = (hf * 2) * ABUF;
            int bl_ = (hf * 2 + 1) * ABUF;
#pragma unroll 2
            for (int ks = 0; ks < 8; ks++) {
                int kw = ks * 8 + tg;
                int rr = m0 + gg;
                unsigned Ah[4], Al[4];
                Ah[0] = sA[bh_ + rr * PITCH + kw];
                Ah[1] = sA[bh_ + (rr + 8) * PITCH + kw];
                Ah[2] = sA[bh_ + rr * PITCH + kw + 4];
                Ah[3] = sA[bh_ + (rr + 8) * PITCH + kw + 4];
                Al[0] = sA[bl_ + rr * PITCH + kw];
                Al[1] = sA[bl_ + (rr + 8) * PITCH + kw];
                Al[2] = sA[bl_ + rr * PITCH + kw + 4];
                Al[3] = sA[bl_ + (rr + 8) * PITCH + kw + 4];
#pragma unroll
                for (int gate = 0; gate < 3; gate++) {
                    const uint4* bp = Bf + (hf * 3 + gate) * 4096 + (pass * 4) * 256 + ks * 32 + lane;
                    uint4 b0 = bp[0];
                    uint4 b1 = bp[256];
                    uint4 b2 = bp[512];
                    uint4 b3 = bp[768];
                    float (*ACC)[4] = (gate == 0) ? aR : (gate == 1) ? aZ : (hf ? aH : aN);
                    mma16816(ACC[0], Ah, b0.x, b0.y);
                    mma16816(ACC[1], Ah, b1.x, b1.y);
                    mma16816(ACC[2], Ah, b2.x, b2.y);
                    mma16816(ACC[3], Ah, b3.x, b3.y);
                    mma16816(ACC[0], Ah, b0.z, b0.w);
                    mma16816(ACC[1], Ah, b1.z, b1.w);
                    mma16816(ACC[2], Ah, b2.z, b2.w);
                    mma16816(ACC[3], Ah, b3.z, b3.w);
                    mma16816(ACC[0], Al, b0.x, b0.y);
                    mma16816(ACC[1], Al, b1.x, b1.y);
                    mma16816(ACC[2], Al, b2.x, b2.y);
                    mma16816(ACC[3], Al, b3.x, b3.y);
                }
            }
        }

        // epilogue for this pass's 32 columns
#pragma unroll
        for (int nt = 0; nt < 4; nt++) {
#pragma unroll
            for (int rh = 0; rh < 2; rh++) {
                int rloc = m0 + rh * 8 + gg;
                int row = n0 + rloc;
                if (row < N) {
                    int col = pass * 32 + nt * 8 + tg * 2;
                    int i0 = rh * 2;
                    float rv0 = aR[nt][i0]     + sbias[col];
                    float rv1 = aR[nt][i0 + 1] + sbias[col + 1];
                    float zv0 = aZ[nt][i0]     + sbias[128 + col];
                    float zv1 = aZ[nt][i0 + 1] + sbias[128 + col + 1];
                    float in0 = aN[nt][i0]     + sbias[256 + col];
                    float in1 = aN[nt][i0 + 1] + sbias[256 + col + 1];
                    float hn0 = aH[nt][i0]     + sbias[384 + col];
                    float hn1 = aH[nt][i0 + 1] + sbias[384 + col + 1];
                    int cw = col >> 1;
                    unsigned wh = sA[2 * ABUF + rloc * PITCH + cw];
                    unsigned wl = sA[3 * ABUF + rloc * PITCH + cw];
                    float2 fh = __bfloat1622float2(*(__nv_bfloat162*)&wh);
                    float2 fl = __bfloat1622float2(*(__nv_bfloat162*)&wl);
                    float hp0 = fh.x + fl.x, hp1 = fh.y + fl.y;
                    float rg0 = 1.f / (1.f + __expf(-rv0));
                    float rg1 = 1.f / (1.f + __expf(-rv1));
                    float zg0 = 1.f / (1.f + __expf(-zv0));
                    float zg1 = 1.f / (1.f + __expf(-zv1));
                    float ng0 = tanhf(fmaf(rg0, hn0, in0));
                    float ng1 = tanhf(fmaf(rg1, hn1, in1));
                    float o0 = fmaf(zg0, hp0 - ng0, ng0);
                    float o1 = fmaf(zg1, hp1 - ng1, ng1);
                    *(float2*)(g_prev + (size_t)row * D + col) = make_float2(o0, o1);
                }
            }
        }
    }
}

// ---------------- decode -------------------------------------------------------------
__global__ void __launch_bounds__(64) dec1_kernel(int N) {
    __shared__ float s_z[DEC_ROWS * D];
    int j = threadIdx.x;
    int n0 = blockIdx.x * DEC_ROWS;
    const float inv6 = 1.f / 6.f;
    for (int i = j; i < DEC_ROWS * D; i += 64) {
        int n = n0 + i / D;
        s_z[i] = (n < N) ? g_hsum[(size_t)n0 * D + i] * inv6 : 0.f;
    }
    __syncthreads();
    float acc[DEC_ROWS];
#pragma unroll
    for (int r = 0; r < DEC_ROWS; r++) acc[r] = 0.f;
#pragma unroll 2
    for (int k = 0; k < D; k++) {
        float w = g_WTd[k * (D / 2) + j];
#pragma unroll
        for (int r = 0; r < DEC_ROWS; r++) acc[r] = fmaf(w, s_z[r * D + k], acc[r]);
    }
    float s = 0.f, sq = 0.f;
#pragma unroll
    for (int r = 0; r < DEC_ROWS; r++) {
        int n = n0 + r;
        if (n < N) {
            g_y0[(size_t)n * (D / 2) + j] = acc[r];
            s += acc[r]; sq += acc[r] * acc[r];
        }
    }
    atomicAdd(&g_stats[2 * D + j], s);
    atomicAdd(&g_stats[2 * D + (D / 2) + j], sq);
}

__global__ void dec2_kernel(const float* __restrict__ gamma, const float* __restrict__ beta,
                            const float* __restrict__ W2, float* __restrict__ out, int N) {
    int warp = (blockIdx.x * blockDim.x + threadIdx.x) >> 5;
    int lane = threadIdx.x & 31;
    if (warp >= N) return;
    float invN = 1.f / (float)N;
    float acc = 0.f;
#pragma unroll
    for (int t = 0; t < 2; t++) {
        int jj = lane + t * 32;
        float mu = g_stats[2 * D + jj] * invN;
        float var = g_stats[2 * D + (D / 2) + jj] * invN - mu * mu;
        float rs = rsqrtf(var + 1e-5f);
        float v = (g_y0[(size_t)warp * (D / 2) + jj] - mu) * rs * gamma[jj] + beta[jj];
        v = v > 0.f ? v : 0.f;
        acc = fmaf(v, W2[jj], acc);
    }
#pragma unroll
    for (int o = 16; o > 0; o >>= 1) acc += __shfl_down_sync(0xffffffffu, acc, o);
    if (lane == 0) out[warp] = acc;
}

// ---------------- launch ----------------------------------------------------------------
extern "C" void kernel_launch(void* const* d_in, const int* in_sizes, int n_in,
                              void* d_out, int out_size) {
    const float* x    = (const float*)d_in[0];
    const int*   ei   = (const int*)d_in[1];
    const float* norm = (const float*)d_in[2];
    const float* Wenc = (const float*)d_in[3];
    const float* beg  = (const float*)d_in[4];
    const float* beb  = (const float*)d_in[5];
    const float* Wih  = (const float*)d_in[6];
    const float* Whh  = (const float*)d_in[7];
    const float* bih  = (const float*)d_in[8];
    const float* bhh  = (const float*)d_in[9];
    const float* Wdec = (const float*)d_in[10];
    const float* bdg  = (const float*)d_in[11];
    const float* bdb  = (const float*)d_in[12];
    const float* W2   = (const float*)d_in[13];

    int N = in_sizes[0] / 3;
    int E = in_sizes[2];
    float* out = (float*)d_out;

    cudaFuncSetAttribute(gru_kernel, cudaFuncAttributeMaxDynamicSharedMemorySize, GRU_SMEM);

    prep_kernel<<<192, 256>>>(Wih, Whh, bih, bhh, Wdec);

    int nb256 = (N + 255) / 256;
    enc_stats_kernel<<<nb256, 128>>>(x, Wenc, N);
    enc_apply_kernel<<<nb256, 128>>>(x, Wenc, beg, beb, N);

    long long sthreads = (long long)E * 32;
    int sb = (int)((sthreads + 255) / 256);
    int gb = (N + 127) / 128;

    for (int L = 0; L < 5; L++) {
        scatter_kernel<<<sb, 256>>>(ei, norm, E);
        gru_kernel<<<gb, 256, GRU_SMEM>>>(N);
    }

    dec1_kernel<<<(N + DEC_ROWS - 1) / DEC_ROWS, 64>>>(N);

    long long d2threads = (long long)N * 32;
    dec2_kernel<<<(int)((d2threads + 255) / 256), 256>>>(bdg, bdb, W2, out, N);
}

// round 7
// speedup vs baseline: 2.0665x; 1.2076x over previous
#include <cuda_runtime.h>
#include <cuda_bf16.h>
#include <math.h>

#define D 128
#define NMAX 50000
#define DEC_ROWS 32

// ---------------- scratch globals ------------------------------------------------
__device__ __align__(16) float g_prev[NMAX * D];
__device__ __align__(16) float g_hsum[NMAX * D];
__device__ __align__(16) float g_hagg[NMAX * D];
__device__ __align__(16) float g_y0[NMAX * (D / 2)];
__device__ __align__(16) float g_stats[2 * D + 2 * (D / 2)];
__device__ __align__(16) float g_WTd[D * (D / 2)];
__device__ __align__(16) float g_bias[512];  // [0,256) r,z combined; [256,384) b_in; [384,512) b_hn
// B fragments: [mat(6: hf*3+gate)][ntile_abs(16)][kstep(8)][lane(32)] -> uint4 {hi.b0,hi.b1,lo.b0,lo.b1}
__device__ __align__(16) uint4 g_Bfrag[6 * 4096];

__device__ __forceinline__ unsigned pack_hi_lo(float x0, float x1, unsigned& lop) {
    __nv_bfloat16 h0 = __float2bfloat16(x0), h1 = __float2bfloat16(x1);
    float l0 = x0 - __bfloat162float(h0), l1 = x1 - __bfloat162float(h1);
    __nv_bfloat16 g0 = __float2bfloat16(l0), g1 = __float2bfloat16(l1);
    lop = ((unsigned)__bfloat16_as_ushort(g1) << 16) | __bfloat16_as_ushort(g0);
    return ((unsigned)__bfloat16_as_ushort(h1) << 16) | __bfloat16_as_ushort(h0);
}

__device__ __forceinline__ void mma16816(float* c, const unsigned* a, unsigned b0, unsigned b1) {
    asm("mma.sync.aligned.m16n8k16.row.col.f32.bf16.bf16.f32 "
        "{%0,%1,%2,%3}, {%4,%5,%6,%7}, {%8,%9}, {%0,%1,%2,%3};"
        : "+f"(c[0]), "+f"(c[1]), "+f"(c[2]), "+f"(c[3])
        : "r"(a[0]), "r"(a[1]), "r"(a[2]), "r"(a[3]), "r"(b0), "r"(b1));
}

// ---------------- prep ------------------------------------------------------------
__global__ void prep_kernel(const float* __restrict__ Wih, const float* __restrict__ Whh,
                            const float* __restrict__ bih, const float* __restrict__ bhh,
                            const float* __restrict__ Wdec) {
    int i = blockIdx.x * blockDim.x + threadIdx.x;
    int stride = gridDim.x * blockDim.x;
    if (i < 384) g_stats[i] = 0.f;
    if (i < 256) g_bias[i] = bih[i] + bhh[i];
    else if (i < 384) g_bias[i] = bih[i];
    if (i >= 384 && i < 512) g_bias[i] = bhh[i - 128];
    for (int idx = i; idx < D * (D / 2); idx += stride) {
        int k = idx / (D / 2), j = idx % (D / 2);
        g_WTd[idx] = Wdec[j * D + k];
    }
    for (int f = i; f < 6 * 4096; f += stride) {
        int lane = f & 31;
        int ks = (f >> 5) & 7;
        int nt = (f >> 8) & 15;
        int mat = f >> 12;
        int hf = mat / 3, gate = mat % 3;
        int gg = lane >> 2, tg = lane & 3;
        int n_local = nt * 8 + gg;
        int k0 = ks * 16 + tg * 2;
        const float* W = hf ? Whh : Wih;
        const float* row = W + (size_t)(gate * 128 + n_local) * D;
        float v00 = row[k0], v01 = row[k0 + 1], v10 = row[k0 + 8], v11 = row[k0 + 9];
        unsigned h0, h1, l0, l1;
        {
            __nv_bfloat16 a = __float2bfloat16(v00), b = __float2bfloat16(v01);
            h0 = ((unsigned)__bfloat16_as_ushort(b) << 16) | __bfloat16_as_ushort(a);
            __nv_bfloat16 la = __float2bfloat16(v00 - __bfloat162float(a));
            __nv_bfloat16 lb = __float2bfloat16(v01 - __bfloat162float(b));
            l0 = ((unsigned)__bfloat16_as_ushort(lb) << 16) | __bfloat16_as_ushort(la);
        }
        {
            __nv_bfloat16 a = __float2bfloat16(v10), b = __float2bfloat16(v11);
            h1 = ((unsigned)__bfloat16_as_ushort(b) << 16) | __bfloat16_as_ushort(a);
            __nv_bfloat16 la = __float2bfloat16(v10 - __bfloat162float(a));
            __nv_bfloat16 lb = __float2bfloat16(v11 - __bfloat162float(b));
            l1 = ((unsigned)__bfloat16_as_ushort(lb) << 16) | __bfloat16_as_ushort(la);
        }
        g_Bfrag[f] = make_uint4(h0, h1, l0, l1);
    }
}

// ---------------- encoder ----------------------------------------------------------
__global__ void enc_stats_kernel(const float* __restrict__ x, const float* __restrict__ Wenc, int N) {
    int d = threadIdx.x;
    float w0 = Wenc[d * 3], w1 = Wenc[d * 3 + 1], w2 = Wenc[d * 3 + 2];
    int n0 = blockIdx.x * 256, lim = min(256, N - n0);
    float s = 0.f, sq = 0.f;
    for (int r = 0; r < lim; r++) {
        int n = n0 + r;
        float h = fmaf(x[n * 3], w0, fmaf(x[n * 3 + 1], w1, x[n * 3 + 2] * w2));
        s += h; sq += h * h;
    }
    atomicAdd(&g_stats[d], s);
    atomicAdd(&g_stats[D + d], sq);
}
__global__ void enc_apply_kernel(const float* __restrict__ x, const float* __restrict__ Wenc,
                                 const float* __restrict__ gamma, const float* __restrict__ beta, int N) {
    int d = threadIdx.x;
    float w0 = Wenc[d * 3], w1 = Wenc[d * 3 + 1], w2 = Wenc[d * 3 + 2];
    float invN = 1.f / (float)N;
    float mu = g_stats[d] * invN;
    float var = g_stats[D + d] * invN - mu * mu;
    float rs = rsqrtf(var + 1e-5f);
    float ga = gamma[d] * rs, be = beta[d] - mu * ga;
    int n0 = blockIdx.x * 256, lim = min(256, N - n0);
    for (int r = 0; r < lim; r++) {
        int n = n0 + r;
        float h = fmaf(x[n * 3], w0, fmaf(x[n * 3 + 1], w1, x[n * 3 + 2] * w2));
        float v = fmaf(h, ga, be);
        v = v > 0.f ? v : 0.f;
        g_prev[(size_t)n * D + d] = v;
        g_hsum[(size_t)n * D + d] = v;
    }
}

// ---------------- dummy (ncu launch alignment: makes launch #5 = first gru) --------
__global__ void dummy_kernel() {}

// ---------------- edge scatter -------------------------------------------------------
__global__ void scatter_kernel(const int* __restrict__ ei, const float* __restrict__ norm, int E) {
    int gw = (blockIdx.x * blockDim.x + threadIdx.x) >> 5;
    int lane = threadIdx.x & 31;
    if (gw >= E) return;
    int s = ei[gw], t = ei[E + gw];
    float nv = norm[gw];
    float4 v = reinterpret_cast<const float4*>(g_prev + (size_t)s * D)[lane];
    v.x *= nv; v.y *= nv; v.z *= nv; v.w *= nv;
    unsigned long long ga = (unsigned long long)__cvta_generic_to_global(g_hagg + (size_t)t * D + lane * 4);
    asm volatile("red.global.add.v4.f32 [%0], {%1,%2,%3,%4};"
                 :: "l"(ga), "f"(v.x), "f"(v.y), "f"(v.z), "f"(v.w) : "memory");
}

// ---------------- GRU: bf16x3 mma.sync, 64 rows/CTA, 8 warps, 2 CTAs/SM ---------------
#define PITCH 68
#define GROWS 64
#define ABUF  (GROWS * PITCH)               // words per A buffer
#define GRU_SMEM (4 * ABUF * 4 + 512 * 4)   // 69632 + 2048 = 71680 B

__global__ void __launch_bounds__(256, 2) gru_kernel(int N) {
    extern __shared__ unsigned char smraw[];
    unsigned* sA = (unsigned*)smraw;
    float* sbias = (float*)(smraw + 4 * ABUF * 4);
    int tid = threadIdx.x;
    int n0 = blockIdx.x * GROWS;

#pragma unroll
    for (int t = 0; t < 2; t++) sbias[t * 256 + tid] = g_bias[t * 256 + tid];

    // conversion: 4 threads/row; hsum += hagg; hagg = 0
    {
        int r = n0 + (tid >> 2);
        int q = tid & 3;
        bool val = r < N;
        const float2* pa = (const float2*)(g_hagg + (size_t)r * D);
        const float2* ph = (const float2*)(g_prev + (size_t)r * D);
        float2* ps = (float2*)(g_hsum + (size_t)r * D);
        float2* pz = (float2*)(g_hagg + (size_t)r * D);
        unsigned base = (tid >> 2) * PITCH;
#pragma unroll 4
        for (int j = 0; j < 16; j++) {
            int kw = 4 * j + q;
            float2 a = val ? pa[kw] : make_float2(0.f, 0.f);
            float2 hh = val ? ph[kw] : make_float2(0.f, 0.f);
            unsigned lo, hi;
            hi = pack_hi_lo(a.x, a.y, lo);
            sA[base + kw] = hi;
            sA[ABUF + base + kw] = lo;
            hi = pack_hi_lo(hh.x, hh.y, lo);
            sA[2 * ABUF + base + kw] = hi;
            sA[3 * ABUF + base + kw] = lo;
            if (val) {
                float2 s = ps[kw];
                ps[kw] = make_float2(s.x + a.x, s.y + a.y);
                pz[kw] = make_float2(0.f, 0.f);
            }
        }
    }
    __syncthreads();

    int lane = tid & 31, wid = tid >> 5;
    int gg = lane >> 2, tg = lane & 3;
    int m0 = (wid & 3) * 16;        // row group: 16 rows
    int pg = wid >> 2;              // pass group: passes {2pg, 2pg+1}
    const uint4* Bf = g_Bfrag;

#pragma unroll 1
    for (int pp = 0; pp < 2; pp++) {
        int pass = 2 * pg + pp;
        float aR[4][4], aZ[4][4], aN[4][4], aH[4][4];
#pragma unroll
        for (int nt = 0; nt < 4; nt++)
#pragma unroll
            for (int q = 0; q < 4; q++) { aR[nt][q] = 0.f; aZ[nt][q] = 0.f; aN[nt][q] = 0.f; aH[nt][q] = 0.f; }

#pragma unroll
        for (int hf = 0; hf < 2; hf++) {
            int bh_ = (hf * 2) * ABUF;
            int bl_ = (hf * 2 + 1) * ABUF;
#pragma unroll 2
            for (int ks = 0; ks < 8; ks++) {
                int kw = ks * 8 + tg;
                int rr = m0 + gg;
                unsigned Ah[4], Al[4];
                Ah[0] = sA[bh_ + rr * PITCH + kw];
                Ah[1] = sA[bh_ + (rr + 8) * PITCH + kw];
                Ah[2] = sA[bh_ + rr * PITCH + kw + 4];
                Ah[3] = sA[bh_ + (rr + 8) * PITCH + kw + 4];
                Al[0] = sA[bl_ + rr * PITCH + kw];
                Al[1] = sA[bl_ + (rr + 8) * PITCH + kw];
                Al[2] = sA[bl_ + rr * PITCH + kw + 4];
                Al[3] = sA[bl_ + (rr + 8) * PITCH + kw + 4];
                const uint4* bp = Bf + hf * 3 * 4096 + pass * 1024 + ks * 32 + lane;
#pragma unroll
                for (int nh = 0; nh < 2; nh++) {
                    // batch 6 independent LDG.128 (3 gates x 2 n-tiles)
                    uint4 b00 = bp[0 * 4096 + (2 * nh + 0) * 256];
                    uint4 b01 = bp[1 * 4096 + (2 * nh + 0) * 256];
                    uint4 b02 = bp[2 * 4096 + (2 * nh + 0) * 256];
                    uint4 b10 = bp[0 * 4096 + (2 * nh + 1) * 256];
                    uint4 b11 = bp[1 * 4096 + (2 * nh + 1) * 256];
                    uint4 b12 = bp[2 * 4096 + (2 * nh + 1) * 256];
                    float (*AN_)[4] = hf ? aH : aN;
                    int t0 = 2 * nh, t1 = 2 * nh + 1;
                    // term 1: hi*hi  (6 independent MMAs)
                    mma16816(aR[t0], Ah, b00.x, b00.y);
                    mma16816(aZ[t0], Ah, b01.x, b01.y);
                    mma16816(AN_[t0], Ah, b02.x, b02.y);
                    mma16816(aR[t1], Ah, b10.x, b10.y);
                    mma16816(aZ[t1], Ah, b11.x, b11.y);
                    mma16816(AN_[t1], Ah, b12.x, b12.y);
                    // term 2: hi*lo
                    mma16816(aR[t0], Ah, b00.z, b00.w);
                    mma16816(aZ[t0], Ah, b01.z, b01.w);
                    mma16816(AN_[t0], Ah, b02.z, b02.w);
                    mma16816(aR[t1], Ah, b10.z, b10.w);
                    mma16816(aZ[t1], Ah, b11.z, b11.w);
                    mma16816(AN_[t1], Ah, b12.z, b12.w);
                    // term 3: lo*hi
                    mma16816(aR[t0], Al, b00.x, b00.y);
                    mma16816(aZ[t0], Al, b01.x, b01.y);
                    mma16816(AN_[t0], Al, b02.x, b02.y);
                    mma16816(aR[t1], Al, b10.x, b10.y);
                    mma16816(aZ[t1], Al, b11.x, b11.y);
                    mma16816(AN_[t1], Al, b12.x, b12.y);
                }
            }
        }

        // epilogue for this pass's 32 columns
#pragma unroll
        for (int nt = 0; nt < 4; nt++) {
#pragma unroll
            for (int rh = 0; rh < 2; rh++) {
                int rloc = m0 + rh * 8 + gg;
                int row = n0 + rloc;
                if (row < N) {
                    int col = pass * 32 + nt * 8 + tg * 2;
                    int i0 = rh * 2;
                    float rv0 = aR[nt][i0]     + sbias[col];
                    float rv1 = aR[nt][i0 + 1] + sbias[col + 1];
                    float zv0 = aZ[nt][i0]     + sbias[128 + col];
                    float zv1 = aZ[nt][i0 + 1] + sbias[128 + col + 1];
                    float in0 = aN[nt][i0]     + sbias[256 + col];
                    float in1 = aN[nt][i0 + 1] + sbias[256 + col + 1];
                    float hn0 = aH[nt][i0]     + sbias[384 + col];
                    float hn1 = aH[nt][i0 + 1] + sbias[384 + col + 1];
                    int cw = col >> 1;
                    unsigned wh = sA[2 * ABUF + rloc * PITCH + cw];
                    unsigned wl = sA[3 * ABUF + rloc * PITCH + cw];
                    float2 fh = __bfloat1622float2(*(__nv_bfloat162*)&wh);
                    float2 fl = __bfloat1622float2(*(__nv_bfloat162*)&wl);
                    float hp0 = fh.x + fl.x, hp1 = fh.y + fl.y;
                    float rg0 = 1.f / (1.f + __expf(-rv0));
                    float rg1 = 1.f / (1.f + __expf(-rv1));
                    float zg0 = 1.f / (1.f + __expf(-zv0));
                    float zg1 = 1.f / (1.f + __expf(-zv1));
                    float ng0 = tanhf(fmaf(rg0, hn0, in0));
                    float ng1 = tanhf(fmaf(rg1, hn1, in1));
                    float o0 = fmaf(zg0, hp0 - ng0, ng0);
                    float o1 = fmaf(zg1, hp1 - ng1, ng1);
                    *(float2*)(g_prev + (size_t)row * D + col) = make_float2(o0, o1);
                }
            }
        }
    }
}

// ---------------- decode -------------------------------------------------------------
__global__ void __launch_bounds__(64) dec1_kernel(int N) {
    __shared__ float s_z[DEC_ROWS * D];
    int j = threadIdx.x;
    int n0 = blockIdx.x * DEC_ROWS;
    const float inv6 = 1.f / 6.f;
    for (int i = j; i < DEC_ROWS * D; i += 64) {
        int n = n0 + i / D;
        s_z[i] = (n < N) ? g_hsum[(size_t)n0 * D + i] * inv6 : 0.f;
    }
    __syncthreads();
    float acc[DEC_ROWS];
#pragma unroll
    for (int r = 0; r < DEC_ROWS; r++) acc[r] = 0.f;
#pragma unroll 2
    for (int k = 0; k < D; k++) {
        float w = g_WTd[k * (D / 2) + j];
#pragma unroll
        for (int r = 0; r < DEC_ROWS; r++) acc[r] = fmaf(w, s_z[r * D + k], acc[r]);
    }
    float s = 0.f, sq = 0.f;
#pragma unroll
    for (int r = 0; r < DEC_ROWS; r++) {
        int n = n0 + r;
        if (n < N) {
            g_y0[(size_t)n * (D / 2) + j] = acc[r];
            s += acc[r]; sq += acc[r] * acc[r];
        }
    }
    atomicAdd(&g_stats[2 * D + j], s);
    atomicAdd(&g_stats[2 * D + (D / 2) + j], sq);
}

__global__ void dec2_kernel(const float* __restrict__ gamma, const float* __restrict__ beta,
                            const float* __restrict__ W2, float* __restrict__ out, int N) {
    int warp = (blockIdx.x * blockDim.x + threadIdx.x) >> 5;
    int lane = threadIdx.x & 31;
    if (warp >= N) return;
    float invN = 1.f / (float)N;
    float acc = 0.f;
#pragma unroll
    for (int t = 0; t < 2; t++) {
        int jj = lane + t * 32;
        float mu = g_stats[2 * D + jj] * invN;
        float var = g_stats[2 * D + (D / 2) + jj] * invN - mu * mu;
        float rs = rsqrtf(var + 1e-5f);
        float v = (g_y0[(size_t)warp * (D / 2) + jj] - mu) * rs * gamma[jj] + beta[jj];
        v = v > 0.f ? v : 0.f;
        acc = fmaf(v, W2[jj], acc);
    }
#pragma unroll
    for (int o = 16; o > 0; o >>= 1) acc += __shfl_down_sync(0xffffffffu, acc, o);
    if (lane == 0) out[warp] = acc;
}

// ---------------- launch ----------------------------------------------------------------
extern "C" void kernel_launch(void* const* d_in, const int* in_sizes, int n_in,
                              void* d_out, int out_size) {
    const float* x    = (const float*)d_in[0];
    const int*   ei   = (const int*)d_in[1];
    const float* norm = (const float*)d_in[2];
    const float* Wenc = (const float*)d_in[3];
    const float* beg  = (const float*)d_in[4];
    const float* beb  = (const float*)d_in[5];
    const float* Wih  = (const float*)d_in[6];
    const float* Whh  = (const float*)d_in[7];
    const float* bih  = (const float*)d_in[8];
    const float* bhh  = (const float*)d_in[9];
    const float* Wdec = (const float*)d_in[10];
    const float* bdg  = (const float*)d_in[11];
    const float* bdb  = (const float*)d_in[12];
    const float* W2   = (const float*)d_in[13];

    int N = in_sizes[0] / 3;
    int E = in_sizes[2];
    float* out = (float*)d_out;

    cudaFuncSetAttribute(gru_kernel, cudaFuncAttributeMaxDynamicSharedMemorySize, GRU_SMEM);

    prep_kernel<<<192, 256>>>(Wih, Whh, bih, bhh, Wdec);

    int nb256 = (N + 255) / 256;
    enc_stats_kernel<<<nb256, 128>>>(x, Wenc, N);
    enc_apply_kernel<<<nb256, 128>>>(x, Wenc, beg, beb, N);

    dummy_kernel<<<1, 32>>>();   // aligns ncu -s 5 -c 1 onto the first gru_kernel

    long long sthreads = (long long)E * 32;
    int sb = (int)((sthreads + 255) / 256);
    int gb = (N + GROWS - 1) / GROWS;

    for (int L = 0; L < 5; L++) {
        scatter_kernel<<<sb, 256>>>(ei, norm, E);
        gru_kernel<<<gb, 256, GRU_SMEM>>>(N);
    }

    dec1_kernel<<<(N + DEC_ROWS - 1) / DEC_ROWS, 64>>>(N);

    long long d2threads = (long long)N * 32;
    dec2_kernel<<<(int)((d2threads + 255) / 256), 256>>>(bdg, bdb, W2, out, N);
}

// round 8
// speedup vs baseline: 2.2969x; 1.1115x over previous
#include <cuda_runtime.h>
#include <cuda_bf16.h>
#include <math.h>

#define D 128
#define NMAX 50000
#define EMAX 640000
#define DEC_ROWS 32

// ---------------- scratch globals ------------------------------------------------
__device__ __align__(16) float g_prev[NMAX * D];
__device__ __align__(16) float g_hsum[NMAX * D];
__device__ __align__(16) float g_hagg[NMAX * D];
__device__ __align__(16) float g_y0[NMAX * (D / 2)];
__device__ __align__(16) float g_stats[2 * D + 2 * (D / 2)];
__device__ __align__(16) float g_WTd[D * (D / 2)];
__device__ __align__(16) float g_bias[512];
__device__ __align__(16) uint4 g_Bfrag[6 * 4096];
// CSR-by-dst (built once per launch; edge_index constant across layers)
__device__ __align__(16) int  g_deg[NMAX];
__device__ __align__(16) int  g_off[NMAX + 1];
__device__ __align__(16) int  g_pos[NMAX];
__device__ __align__(16) uint2 g_edge[EMAX];   // {src, norm_bits}

__device__ __forceinline__ unsigned pack_hi_lo(float x0, float x1, unsigned& lop) {
    __nv_bfloat16 h0 = __float2bfloat16(x0), h1 = __float2bfloat16(x1);
    float l0 = x0 - __bfloat162float(h0), l1 = x1 - __bfloat162float(h1);
    __nv_bfloat16 g0 = __float2bfloat16(l0), g1 = __float2bfloat16(l1);
    lop = ((unsigned)__bfloat16_as_ushort(g1) << 16) | __bfloat16_as_ushort(g0);
    return ((unsigned)__bfloat16_as_ushort(h1) << 16) | __bfloat16_as_ushort(h0);
}

__device__ __forceinline__ void mma16816(float* c, const unsigned* a, unsigned b0, unsigned b1) {
    asm("mma.sync.aligned.m16n8k16.row.col.f32.bf16.bf16.f32 "
        "{%0,%1,%2,%3}, {%4,%5,%6,%7}, {%8,%9}, {%0,%1,%2,%3};"
        : "+f"(c[0]), "+f"(c[1]), "+f"(c[2]), "+f"(c[3])
        : "r"(a[0]), "r"(a[1]), "r"(a[2]), "r"(a[3]), "r"(b0), "r"(b1));
}

// ---------------- prep ------------------------------------------------------------
__global__ void prep_kernel(const float* __restrict__ Wih, const float* __restrict__ Whh,
                            const float* __restrict__ bih, const float* __restrict__ bhh,
                            const float* __restrict__ Wdec, int N) {
    int i = blockIdx.x * blockDim.x + threadIdx.x;
    int stride = gridDim.x * blockDim.x;
    if (i < 384) g_stats[i] = 0.f;
    if (i < 256) g_bias[i] = bih[i] + bhh[i];
    else if (i < 384) g_bias[i] = bih[i];
    if (i >= 384 && i < 512) g_bias[i] = bhh[i - 128];
    for (int idx = i; idx < N; idx += stride) g_deg[idx] = 0;
    for (int idx = i; idx < D * (D / 2); idx += stride) {
        int k = idx / (D / 2), j = idx % (D / 2);
        g_WTd[idx] = Wdec[j * D + k];
    }
    for (int f = i; f < 6 * 4096; f += stride) {
        int lane = f & 31;
        int ks = (f >> 5) & 7;
        int nt = (f >> 8) & 15;
        int mat = f >> 12;
        int hf = mat / 3, gate = mat % 3;
        int gg = lane >> 2, tg = lane & 3;
        int n_local = nt * 8 + gg;
        int k0 = ks * 16 + tg * 2;
        const float* W = hf ? Whh : Wih;
        const float* row = W + (size_t)(gate * 128 + n_local) * D;
        float v00 = row[k0], v01 = row[k0 + 1], v10 = row[k0 + 8], v11 = row[k0 + 9];
        unsigned h0, h1, l0, l1;
        {
            __nv_bfloat16 a = __float2bfloat16(v00), b = __float2bfloat16(v01);
            h0 = ((unsigned)__bfloat16_as_ushort(b) << 16) | __bfloat16_as_ushort(a);
            __nv_bfloat16 la = __float2bfloat16(v00 - __bfloat162float(a));
            __nv_bfloat16 lb = __float2bfloat16(v01 - __bfloat162float(b));
            l0 = ((unsigned)__bfloat16_as_ushort(lb) << 16) | __bfloat16_as_ushort(la);
        }
        {
            __nv_bfloat16 a = __float2bfloat16(v10), b = __float2bfloat16(v11);
            h1 = ((unsigned)__bfloat16_as_ushort(b) << 16) | __bfloat16_as_ushort(a);
            __nv_bfloat16 la = __float2bfloat16(v10 - __bfloat162float(a));
            __nv_bfloat16 lb = __float2bfloat16(v11 - __bfloat162float(b));
            l1 = ((unsigned)__bfloat16_as_ushort(lb) << 16) | __bfloat16_as_ushort(la);
        }
        g_Bfrag[f] = make_uint4(h0, h1, l0, l1);
    }
}

// ---------------- CSR build (once per launch) ---------------------------------------
__global__ void count_kernel(const int* __restrict__ ei, int E) {
    int i = blockIdx.x * blockDim.x + threadIdx.x;
    if (i < E) atomicAdd(&g_deg[ei[E + i]], 1);
}

__global__ void __launch_bounds__(1024) scan_kernel(int N) {
    __shared__ int s[1024];
    int tid = threadIdx.x;
    int chunk = (N + 1023) / 1024;
    int start = tid * chunk;
    int end = min(start + chunk, N);
    int sum = 0;
    for (int i = start; i < end; i++) sum += g_deg[i];
    s[tid] = sum;
    __syncthreads();
    for (int off = 1; off < 1024; off <<= 1) {
        int v = (tid >= off) ? s[tid - off] : 0;
        __syncthreads();
        s[tid] += v;
        __syncthreads();
    }
    int run = (tid == 0) ? 0 : s[tid - 1];
    for (int i = start; i < end; i++) {
        g_off[i] = run;
        g_pos[i] = run;
        run += g_deg[i];
    }
    if (end == N && start <= N) g_off[N] = run;
}

__global__ void fill_kernel(const int* __restrict__ ei, const float* __restrict__ norm, int E) {
    int i = blockIdx.x * blockDim.x + threadIdx.x;
    if (i < E) {
        int t = ei[E + i];
        int p = atomicAdd(&g_pos[t], 1);
        g_edge[p] = make_uint2((unsigned)ei[i], __float_as_uint(norm[i]));
    }
}

// ---------------- encoder ----------------------------------------------------------
__global__ void enc_stats_kernel(const float* __restrict__ x, const float* __restrict__ Wenc, int N) {
    int d = threadIdx.x;
    float w0 = Wenc[d * 3], w1 = Wenc[d * 3 + 1], w2 = Wenc[d * 3 + 2];
    int n0 = blockIdx.x * 256, lim = min(256, N - n0);
    float s = 0.f, sq = 0.f;
    for (int r = 0; r < lim; r++) {
        int n = n0 + r;
        float h = fmaf(x[n * 3], w0, fmaf(x[n * 3 + 1], w1, x[n * 3 + 2] * w2));
        s += h; sq += h * h;
    }
    atomicAdd(&g_stats[d], s);
    atomicAdd(&g_stats[D + d], sq);
}
__global__ void enc_apply_kernel(const float* __restrict__ x, const float* __restrict__ Wenc,
                                 const float* __restrict__ gamma, const float* __restrict__ beta, int N) {
    int d = threadIdx.x;
    float w0 = Wenc[d * 3], w1 = Wenc[d * 3 + 1], w2 = Wenc[d * 3 + 2];
    float invN = 1.f / (float)N;
    float mu = g_stats[d] * invN;
    float var = g_stats[D + d] * invN - mu * mu;
    float rs = rsqrtf(var + 1e-5f);
    float ga = gamma[d] * rs, be = beta[d] - mu * ga;
    int n0 = blockIdx.x * 256, lim = min(256, N - n0);
    for (int r = 0; r < lim; r++) {
        int n = n0 + r;
        float h = fmaf(x[n * 3], w0, fmaf(x[n * 3 + 1], w1, x[n * 3 + 2] * w2));
        float v = fmaf(h, ga, be);
        v = v > 0.f ? v : 0.f;
        g_prev[(size_t)n * D + d] = v;
        g_hsum[(size_t)n * D + d] = v;
    }
}

// ---------------- gather aggregation: h_agg[n] = sum_{e: dst=n} norm_e * prev[src_e] --
__global__ void __launch_bounds__(256) gather_kernel(int N) {
    int gw = (blockIdx.x * blockDim.x + threadIdx.x) >> 5;
    int lane = threadIdx.x & 31;
    if (gw >= N) return;
    int beg = g_off[gw], end = g_off[gw + 1];
    const float4* prev4 = (const float4*)g_prev;
    float4 acc = make_float4(0.f, 0.f, 0.f, 0.f);
    int j = beg;
    for (; j + 1 < end; j += 2) {
        uint2 e0 = g_edge[j];
        uint2 e1 = g_edge[j + 1];
        float4 v0 = prev4[(size_t)e0.x * 32 + lane];
        float4 v1 = prev4[(size_t)e1.x * 32 + lane];
        float nv0 = __uint_as_float(e0.y), nv1 = __uint_as_float(e1.y);
        acc.x = fmaf(nv0, v0.x, fmaf(nv1, v1.x, acc.x));
        acc.y = fmaf(nv0, v0.y, fmaf(nv1, v1.y, acc.y));
        acc.z = fmaf(nv0, v0.z, fmaf(nv1, v1.z, acc.z));
        acc.w = fmaf(nv0, v0.w, fmaf(nv1, v1.w, acc.w));
    }
    if (j < end) {
        uint2 e0 = g_edge[j];
        float4 v0 = prev4[(size_t)e0.x * 32 + lane];
        float nv0 = __uint_as_float(e0.y);
        acc.x = fmaf(nv0, v0.x, acc.x);
        acc.y = fmaf(nv0, v0.y, acc.y);
        acc.z = fmaf(nv0, v0.z, acc.z);
        acc.w = fmaf(nv0, v0.w, acc.w);
    }
    ((float4*)g_hagg)[(size_t)gw * 32 + lane] = acc;
}

// ---------------- GRU: bf16x3 mma.sync, 64 rows/CTA, 8 warps, 2 CTAs/SM ---------------
#define PITCH 68
#define GROWS 64
#define ABUF  (GROWS * PITCH)
#define GRU_SMEM (4 * ABUF * 4 + 512 * 4)

__global__ void __launch_bounds__(256, 2) gru_kernel(int N) {
    extern __shared__ unsigned char smraw[];
    unsigned* sA = (unsigned*)smraw;
    float* sbias = (float*)(smraw + 4 * ABUF * 4);
    int tid = threadIdx.x;
    int n0 = blockIdx.x * GROWS;

#pragma unroll
    for (int t = 0; t < 2; t++) sbias[t * 256 + tid] = g_bias[t * 256 + tid];

    // conversion: 4 threads/row; hsum += hagg (no hagg clear needed: gather overwrites)
    {
        int r = n0 + (tid >> 2);
        int q = tid & 3;
        bool val = r < N;
        const float2* pa = (const float2*)(g_hagg + (size_t)r * D);
        const float2* ph = (const float2*)(g_prev + (size_t)r * D);
        float2* ps = (float2*)(g_hsum + (size_t)r * D);
        unsigned base = (tid >> 2) * PITCH;
#pragma unroll 4
        for (int j = 0; j < 16; j++) {
            int kw = 4 * j + q;
            float2 a = val ? pa[kw] : make_float2(0.f, 0.f);
            float2 hh = val ? ph[kw] : make_float2(0.f, 0.f);
            unsigned lo, hi;
            hi = pack_hi_lo(a.x, a.y, lo);
            sA[base + kw] = hi;
            sA[ABUF + base + kw] = lo;
            hi = pack_hi_lo(hh.x, hh.y, lo);
            sA[2 * ABUF + base + kw] = hi;
            sA[3 * ABUF + base + kw] = lo;
            if (val) {
                float2 s = ps[kw];
                ps[kw] = make_float2(s.x + a.x, s.y + a.y);
            }
        }
    }
    __syncthreads();

    int lane = tid & 31, wid = tid >> 5;
    int gg = lane >> 2, tg = lane & 3;
    int m0 = (wid & 3) * 16;
    int pg = wid >> 2;
    const uint4* Bf = g_Bfrag;

#pragma unroll 1
    for (int pp = 0; pp < 2; pp++) {
        int pass = 2 * pg + pp;
        float aR[4][4], aZ[4][4], aN[4][4], aH[4][4];
#pragma unroll
        for (int nt = 0; nt < 4; nt++)
#pragma unroll
            for (int q = 0; q < 4; q++) { aR[nt][q] = 0.f; aZ[nt][q] = 0.f; aN[nt][q] = 0.f; aH[nt][q] = 0.f; }

#pragma unroll
        for (int hf = 0; hf < 2; hf++) {
            int bh_ = (hf * 2) * ABUF;
            int bl_ = (hf * 2 + 1) * ABUF;
#pragma unroll 2
            for (int ks = 0; ks < 8; ks++) {
                int kw = ks * 8 + tg;
                int rr = m0 + gg;
                unsigned Ah[4], Al[4];
                Ah[0] = sA[bh_ + rr * PITCH + kw];
                Ah[1] = sA[bh_ + (rr + 8) * PITCH + kw];
                Ah[2] = sA[bh_ + rr * PITCH + kw + 4];
                Ah[3] = sA[bh_ + (rr + 8) * PITCH + kw + 4];
                Al[0] = sA[bl_ + rr * PITCH + kw];
                Al[1] = sA[bl_ + (rr + 8) * PITCH + kw];
                Al[2] = sA[bl_ + rr * PITCH + kw + 4];
                Al[3] = sA[bl_ + (rr + 8) * PITCH + kw + 4];
                const uint4* bp = Bf + hf * 3 * 4096 + pass * 1024 + ks * 32 + lane;
#pragma unroll
                for (int nh = 0; nh < 2; nh++) {
                    uint4 b00 = bp[0 * 4096 + (2 * nh + 0) * 256];
                    uint4 b01 = bp[1 * 4096 + (2 * nh + 0) * 256];
                    uint4 b02 = bp[2 * 4096 + (2 * nh + 0) * 256];
                    uint4 b10 = bp[0 * 4096 + (2 * nh + 1) * 256];
                    uint4 b11 = bp[1 * 4096 + (2 * nh + 1) * 256];
                    uint4 b12 = bp[2 * 4096 + (2 * nh + 1) * 256];
                    float (*AN_)[4] = hf ? aH : aN;
                    int t0 = 2 * nh, t1 = 2 * nh + 1;
                    mma16816(aR[t0], Ah, b00.x, b00.y);
                    mma16816(aZ[t0], Ah, b01.x, b01.y);
                    mma16816(AN_[t0], Ah, b02.x, b02.y);
                    mma16816(aR[t1], Ah, b10.x, b10.y);
                    mma16816(aZ[t1], Ah, b11.x, b11.y);
                    mma16816(AN_[t1], Ah, b12.x, b12.y);
                    mma16816(aR[t0], Ah, b00.z, b00.w);
                    mma16816(aZ[t0], Ah, b01.z, b01.w);
                    mma16816(AN_[t0], Ah, b02.z, b02.w);
                    mma16816(aR[t1], Ah, b10.z, b10.w);
                    mma16816(aZ[t1], Ah, b11.z, b11.w);
                    mma16816(AN_[t1], Ah, b12.z, b12.w);
                    mma16816(aR[t0], Al, b00.x, b00.y);
                    mma16816(aZ[t0], Al, b01.x, b01.y);
                    mma16816(AN_[t0], Al, b02.x, b02.y);
                    mma16816(aR[t1], Al, b10.x, b10.y);
                    mma16816(aZ[t1], Al, b11.x, b11.y);
                    mma16816(AN_[t1], Al, b12.x, b12.y);
                }
            }
        }

#pragma unroll
        for (int nt = 0; nt < 4; nt++) {
#pragma unroll
            for (int rh = 0; rh < 2; rh++) {
                int rloc = m0 + rh * 8 + gg;
                int row = n0 + rloc;
                if (row < N) {
                    int col = pass * 32 + nt * 8 + tg * 2;
                    int i0 = rh * 2;
                    float rv0 = aR[nt][i0]     + sbias[col];
                    float rv1 = aR[nt][i0 + 1] + sbias[col + 1];
                    float zv0 = aZ[nt][i0]     + sbias[128 + col];
                    float zv1 = aZ[nt][i0 + 1] + sbias[128 + col + 1];
                    float in0 = aN[nt][i0]     + sbias[256 + col];
                    float in1 = aN[nt][i0 + 1] + sbias[256 + col + 1];
                    float hn0 = aH[nt][i0]     + sbias[384 + col];
                    float hn1 = aH[nt][i0 + 1] + sbias[384 + col + 1];
                    int cw = col >> 1;
                    unsigned wh = sA[2 * ABUF + rloc * PITCH + cw];
                    unsigned wl = sA[3 * ABUF + rloc * PITCH + cw];
                    float2 fh = __bfloat1622float2(*(__nv_bfloat162*)&wh);
                    float2 fl = __bfloat1622float2(*(__nv_bfloat162*)&wl);
                    float hp0 = fh.x + fl.x, hp1 = fh.y + fl.y;
                    float rg0 = 1.f / (1.f + __expf(-rv0));
                    float rg1 = 1.f / (1.f + __expf(-rv1));
                    float zg0 = 1.f / (1.f + __expf(-zv0));
                    float zg1 = 1.f / (1.f + __expf(-zv1));
                    float ng0 = tanhf(fmaf(rg0, hn0, in0));
                    float ng1 = tanhf(fmaf(rg1, hn1, in1));
                    float o0 = fmaf(zg0, hp0 - ng0, ng0);
                    float o1 = fmaf(zg1, hp1 - ng1, ng1);
                    *(float2*)(g_prev + (size_t)row * D + col) = make_float2(o0, o1);
                }
            }
        }
    }
}

// ---------------- decode -------------------------------------------------------------
__global__ void __launch_bounds__(64) dec1_kernel(int N) {
    __shared__ float s_z[DEC_ROWS * D];
    int j = threadIdx.x;
    int n0 = blockIdx.x * DEC_ROWS;
    const float inv6 = 1.f / 6.f;
    for (int i = j; i < DEC_ROWS * D; i += 64) {
        int n = n0 + i / D;
        s_z[i] = (n < N) ? g_hsum[(size_t)n0 * D + i] * inv6 : 0.f;
    }
    __syncthreads();
    float acc[DEC_ROWS];
#pragma unroll
    for (int r = 0; r < DEC_ROWS; r++) acc[r] = 0.f;
#pragma unroll 2
    for (int k = 0; k < D; k++) {
        float w = g_WTd[k * (D / 2) + j];
#pragma unroll
        for (int r = 0; r < DEC_ROWS; r++) acc[r] = fmaf(w, s_z[r * D + k], acc[r]);
    }
    float s = 0.f, sq = 0.f;
#pragma unroll
    for (int r = 0; r < DEC_ROWS; r++) {
        int n = n0 + r;
        if (n < N) {
            g_y0[(size_t)n * (D / 2) + j] = acc[r];
            s += acc[r]; sq += acc[r] * acc[r];
        }
    }
    atomicAdd(&g_stats[2 * D + j], s);
    atomicAdd(&g_stats[2 * D + (D / 2) + j], sq);
}

__global__ void dec2_kernel(const float* __restrict__ gamma, const float* __restrict__ beta,
                            const float* __restrict__ W2, float* __restrict__ out, int N) {
    int warp = (blockIdx.x * blockDim.x + threadIdx.x) >> 5;
    int lane = threadIdx.x & 31;
    if (warp >= N) return;
    float invN = 1.f / (float)N;
    float acc = 0.f;
#pragma unroll
    for (int t = 0; t < 2; t++) {
        int jj = lane + t * 32;
        float mu = g_stats[2 * D + jj] * invN;
        float var = g_stats[2 * D + (D / 2) + jj] * invN - mu * mu;
        float rs = rsqrtf(var + 1e-5f);
        float v = (g_y0[(size_t)warp * (D / 2) + jj] - mu) * rs * gamma[jj] + beta[jj];
        v = v > 0.f ? v : 0.f;
        acc = fmaf(v, W2[jj], acc);
    }
#pragma unroll
    for (int o = 16; o > 0; o >>= 1) acc += __shfl_down_sync(0xffffffffu, acc, o);
    if (lane == 0) out[warp] = acc;
}

// ---------------- launch ----------------------------------------------------------------
extern "C" void kernel_launch(void* const* d_in, const int* in_sizes, int n_in,
                              void* d_out, int out_size) {
    const float* x    = (const float*)d_in[0];
    const int*   ei   = (const int*)d_in[1];
    const float* norm = (const float*)d_in[2];
    const float* Wenc = (const float*)d_in[3];
    const float* beg  = (const float*)d_in[4];
    const float* beb  = (const float*)d_in[5];
    const float* Wih  = (const float*)d_in[6];
    const float* Whh  = (const float*)d_in[7];
    const float* bih  = (const float*)d_in[8];
    const float* bhh  = (const float*)d_in[9];
    const float* Wdec = (const float*)d_in[10];
    const float* bdg  = (const float*)d_in[11];
    const float* bdb  = (const float*)d_in[12];
    const float* W2   = (const float*)d_in[13];

    int N = in_sizes[0] / 3;
    int E = in_sizes[2];
    float* out = (float*)d_out;

    cudaFuncSetAttribute(gru_kernel, cudaFuncAttributeMaxDynamicSharedMemorySize, GRU_SMEM);

    prep_kernel<<<192, 256>>>(Wih, Whh, bih, bhh, Wdec, N);
    count_kernel<<<(E + 255) / 256, 256>>>(ei, E);
    scan_kernel<<<1, 1024>>>(N);
    fill_kernel<<<(E + 255) / 256, 256>>>(ei, norm, E);

    int nb256 = (N + 255) / 256;
    enc_stats_kernel<<<nb256, 128>>>(x, Wenc, N);
    enc_apply_kernel<<<nb256, 128>>>(x, Wenc, beg, beb, N);

    int gthreads_blocks = (N * 32 + 255) / 256;
    int gb = (N + GROWS - 1) / GROWS;

    for (int L = 0; L < 5; L++) {
        gather_kernel<<<gthreads_blocks, 256>>>(N);
        gru_kernel<<<gb, 256, GRU_SMEM>>>(N);
    }

    dec1_kernel<<<(N + DEC_ROWS - 1) / DEC_ROWS, 64>>>(N);

    long long d2threads = (long long)N * 32;
    dec2_kernel<<<(int)((d2threads + 255) / 256), 256>>>(bdg, bdb, W2, out, N);
}

// round 10
// speedup vs baseline: 2.5165x; 1.0956x over previous
#include <cuda_runtime.h>
#include <cuda_bf16.h>
#include <math.h>

#define D 128
#define NMAX 50000
#define EMAX 640000
#define DEC_ROWS 32

// ---------------- scratch globals ------------------------------------------------
__device__ __align__(16) float g_prevA[NMAX * D];
__device__ __align__(16) float g_prevB[NMAX * D];
__device__ __align__(16) float g_hsum[NMAX * D];
__device__ __align__(16) float g_y0[NMAX * (D / 2)];
__device__ __align__(16) float g_stats[2 * D + 2 * (D / 2)];
__device__ __align__(16) float g_WTd[D * (D / 2)];
__device__ __align__(16) float g_bias[512];
__device__ __align__(16) uint4 g_Bfrag[6 * 4096];
// CSR-by-dst
__device__ __align__(16) int  g_deg[NMAX];
__device__ __align__(16) int  g_off[NMAX + 1];
__device__ __align__(16) int  g_pos[NMAX];
__device__ __align__(16) uint2 g_edge[EMAX];   // {src, norm_bits}

__device__ __forceinline__ unsigned pack_hi_lo(float x0, float x1, unsigned& lop) {
    __nv_bfloat16 h0 = __float2bfloat16(x0), h1 = __float2bfloat16(x1);
    float l0 = x0 - __bfloat162float(h0), l1 = x1 - __bfloat162float(h1);
    __nv_bfloat16 g0 = __float2bfloat16(l0), g1 = __float2bfloat16(l1);
    lop = ((unsigned)__bfloat16_as_ushort(g1) << 16) | __bfloat16_as_ushort(g0);
    return ((unsigned)__bfloat16_as_ushort(h1) << 16) | __bfloat16_as_ushort(h0);
}

__device__ __forceinline__ void mma16816(float* c, const unsigned* a, unsigned b0, unsigned b1) {
    asm("mma.sync.aligned.m16n8k16.row.col.f32.bf16.bf16.f32 "
        "{%0,%1,%2,%3}, {%4,%5,%6,%7}, {%8,%9}, {%0,%1,%2,%3};"
        : "+f"(c[0]), "+f"(c[1]), "+f"(c[2]), "+f"(c[3])
        : "r"(a[0]), "r"(a[1]), "r"(a[2]), "r"(a[3]), "r"(b0), "r"(b1));
}

__device__ __forceinline__ float fast_sigmoid(float x) {
    return __fdividef(1.f, 1.f + __expf(-x));
}
__device__ __forceinline__ float fast_tanh(float x) {
    float e = __expf(2.f * x);
    return 1.f - __fdividef(2.f, e + 1.f);
}

// ---------------- prep ------------------------------------------------------------
__global__ void prep_kernel(const float* __restrict__ Wih, const float* __restrict__ Whh,
                            const float* __restrict__ bih, const float* __restrict__ bhh,
                            const float* __restrict__ Wdec, int N) {
    int i = blockIdx.x * blockDim.x + threadIdx.x;
    int stride = gridDim.x * blockDim.x;
    if (i < 384) g_stats[i] = 0.f;
    if (i < 256) g_bias[i] = bih[i] + bhh[i];
    else if (i < 384) g_bias[i] = bih[i];
    if (i >= 384 && i < 512) g_bias[i] = bhh[i - 128];
    for (int idx = i; idx < N; idx += stride) g_deg[idx] = 0;
    for (int idx = i; idx < D * (D / 2); idx += stride) {
        int k = idx / (D / 2), j = idx % (D / 2);
        g_WTd[idx] = Wdec[j * D + k];
    }
    for (int f = i; f < 6 * 4096; f += stride) {
        int lane = f & 31;
        int ks = (f >> 5) & 7;
        int nt = (f >> 8) & 15;
        int mat = f >> 12;
        int hf = mat / 3, gate = mat % 3;
        int gg = lane >> 2, tg = lane & 3;
        int n_local = nt * 8 + gg;
        int k0 = ks * 16 + tg * 2;
        const float* W = hf ? Whh : Wih;
        const float* row = W + (size_t)(gate * 128 + n_local) * D;
        float v00 = row[k0], v01 = row[k0 + 1], v10 = row[k0 + 8], v11 = row[k0 + 9];
        unsigned h0, h1, l0, l1;
        {
            __nv_bfloat16 a = __float2bfloat16(v00), b = __float2bfloat16(v01);
            h0 = ((unsigned)__bfloat16_as_ushort(b) << 16) | __bfloat16_as_ushort(a);
            __nv_bfloat16 la = __float2bfloat16(v00 - __bfloat162float(a));
            __nv_bfloat16 lb = __float2bfloat16(v01 - __bfloat162float(b));
            l0 = ((unsigned)__bfloat16_as_ushort(lb) << 16) | __bfloat16_as_ushort(la);
        }
        {
            __nv_bfloat16 a = __float2bfloat16(v10), b = __float2bfloat16(v11);
            h1 = ((unsigned)__bfloat16_as_ushort(b) << 16) | __bfloat16_as_ushort(a);
            __nv_bfloat16 la = __float2bfloat16(v10 - __bfloat162float(a));
            __nv_bfloat16 lb = __float2bfloat16(v11 - __bfloat162float(b));
            l1 = ((unsigned)__bfloat16_as_ushort(lb) << 16) | __bfloat16_as_ushort(la);
        }
        g_Bfrag[f] = make_uint4(h0, h1, l0, l1);
    }
}

// ---------------- CSR build --------------------------------------------------------
__global__ void count_kernel(const int* __restrict__ ei, int E) {
    int i = blockIdx.x * blockDim.x + threadIdx.x;
    if (i < E) atomicAdd(&g_deg[ei[E + i]], 1);
}

__global__ void __launch_bounds__(1024) scan_kernel(int N) {
    __shared__ int s[1024];
    int tid = threadIdx.x;
    int chunk = (N + 1023) / 1024;
    int start = tid * chunk;
    int end = min(start + chunk, N);
    int sum = 0;
    for (int i = start; i < end; i++) sum += g_deg[i];
    s[tid] = sum;
    __syncthreads();
    for (int off = 1; off < 1024; off <<= 1) {
        int v = (tid >= off) ? s[tid - off] : 0;
        __syncthreads();
        s[tid] += v;
        __syncthreads();
    }
    int run = (tid == 0) ? 0 : s[tid - 1];
    for (int i = start; i < end; i++) {
        g_off[i] = run;
        g_pos[i] = run;
        run += g_deg[i];
    }
    if (end == N && start <= N) g_off[N] = run;
}

__global__ void fill_kernel(const int* __restrict__ ei, const float* __restrict__ norm, int E) {
    int i = blockIdx.x * blockDim.x + threadIdx.x;
    if (i < E) {
        int t = ei[E + i];
        int p = atomicAdd(&g_pos[t], 1);
        g_edge[p] = make_uint2((unsigned)ei[i], __float_as_uint(norm[i]));
    }
}

// ---------------- encoder ----------------------------------------------------------
__global__ void enc_stats_kernel(const float* __restrict__ x, const float* __restrict__ Wenc, int N) {
    int d = threadIdx.x;
    float w0 = Wenc[d * 3], w1 = Wenc[d * 3 + 1], w2 = Wenc[d * 3 + 2];
    int n0 = blockIdx.x * 256, lim = min(256, N - n0);
    float s = 0.f, sq = 0.f;
    for (int r = 0; r < lim; r++) {
        int n = n0 + r;
        float h = fmaf(x[n * 3], w0, fmaf(x[n * 3 + 1], w1, x[n * 3 + 2] * w2));
        s += h; sq += h * h;
    }
    atomicAdd(&g_stats[d], s);
    atomicAdd(&g_stats[D + d], sq);
}
__global__ void enc_apply_kernel(const float* __restrict__ x, const float* __restrict__ Wenc,
                                 const float* __restrict__ gamma, const float* __restrict__ beta, int N) {
    int d = threadIdx.x;
    float w0 = Wenc[d * 3], w1 = Wenc[d * 3 + 1], w2 = Wenc[d * 3 + 2];
    float invN = 1.f / (float)N;
    float mu = g_stats[d] * invN;
    float var = g_stats[D + d] * invN - mu * mu;
    float rs = rsqrtf(var + 1e-5f);
    float ga = gamma[d] * rs, be = beta[d] - mu * ga;
    int n0 = blockIdx.x * 256, lim = min(256, N - n0);
    for (int r = 0; r < lim; r++) {
        int n = n0 + r;
        float h = fmaf(x[n * 3], w0, fmaf(x[n * 3 + 1], w1, x[n * 3 + 2] * w2));
        float v = fmaf(h, ga, be);
        v = v > 0.f ? v : 0.f;
        g_prevA[(size_t)n * D + d] = v;
        g_hsum[(size_t)n * D + d] = v;
    }
}

// ---------------- fused layer: gather + GRU, double-buffered prev -------------------
#define PITCH 68
#define GROWS 64
#define ABUF  (GROWS * PITCH)
#define GRU_SMEM (4 * ABUF * 4 + 512 * 4)

__global__ void __launch_bounds__(256, 2) layer_kernel(const float* __restrict__ prev_in,
                                                       float* __restrict__ prev_out, int N) {
    extern __shared__ unsigned char smraw[];
    unsigned* sA = (unsigned*)smraw;
    float* sbias = (float*)(smraw + 4 * ABUF * 4);
    int tid = threadIdx.x;
    int n0 = blockIdx.x * GROWS;
    int lane = tid & 31, wid = tid >> 5;

#pragma unroll
    for (int t = 0; t < 2; t++) sbias[t * 256 + tid] = g_bias[t * 256 + tid];

    // --- fused gather + convert: warp w handles rows [w*8, w*8+8); reads prev_in only ---
    const float4* prev4 = (const float4*)prev_in;
#pragma unroll 1
    for (int rr = 0; rr < 8; rr++) {
        int rloc = wid * 8 + rr;
        int row = n0 + rloc;
        float4 acc = make_float4(0.f, 0.f, 0.f, 0.f);
        float4 hv = make_float4(0.f, 0.f, 0.f, 0.f);
        if (row < N) {
            int beg = g_off[row], end = g_off[row + 1];
            int j = beg;
            for (; j + 3 < end; j += 4) {
                uint2 e0 = g_edge[j], e1 = g_edge[j + 1], e2 = g_edge[j + 2], e3 = g_edge[j + 3];
                float4 v0 = prev4[(size_t)e0.x * 32 + lane];
                float4 v1 = prev4[(size_t)e1.x * 32 + lane];
                float4 v2 = prev4[(size_t)e2.x * 32 + lane];
                float4 v3 = prev4[(size_t)e3.x * 32 + lane];
                float n0v = __uint_as_float(e0.y), n1v = __uint_as_float(e1.y);
                float n2v = __uint_as_float(e2.y), n3v = __uint_as_float(e3.y);
                acc.x = fmaf(n0v, v0.x, fmaf(n1v, v1.x, fmaf(n2v, v2.x, fmaf(n3v, v3.x, acc.x))));
                acc.y = fmaf(n0v, v0.y, fmaf(n1v, v1.y, fmaf(n2v, v2.y, fmaf(n3v, v3.y, acc.y))));
                acc.z = fmaf(n0v, v0.z, fmaf(n1v, v1.z, fmaf(n2v, v2.z, fmaf(n3v, v3.z, acc.z))));
                acc.w = fmaf(n0v, v0.w, fmaf(n1v, v1.w, fmaf(n2v, v2.w, fmaf(n3v, v3.w, acc.w))));
            }
            for (; j < end; j++) {
                uint2 e0 = g_edge[j];
                float4 v0 = prev4[(size_t)e0.x * 32 + lane];
                float nv = __uint_as_float(e0.y);
                acc.x = fmaf(nv, v0.x, acc.x);
                acc.y = fmaf(nv, v0.y, acc.y);
                acc.z = fmaf(nv, v0.z, acc.z);
                acc.w = fmaf(nv, v0.w, acc.w);
            }
            hv = prev4[(size_t)row * 32 + lane];
            float4 sv = ((const float4*)g_hsum)[(size_t)row * 32 + lane];
            ((float4*)g_hsum)[(size_t)row * 32 + lane] =
                make_float4(sv.x + acc.x, sv.y + acc.y, sv.z + acc.z, sv.w + acc.w);
        }
        unsigned base = rloc * PITCH + lane * 2;
        unsigned lo, hi;
        hi = pack_hi_lo(acc.x, acc.y, lo);
        sA[base] = hi; sA[ABUF + base] = lo;
        hi = pack_hi_lo(acc.z, acc.w, lo);
        sA[base + 1] = hi; sA[ABUF + base + 1] = lo;
        hi = pack_hi_lo(hv.x, hv.y, lo);
        sA[2 * ABUF + base] = hi; sA[3 * ABUF + base] = lo;
        hi = pack_hi_lo(hv.z, hv.w, lo);
        sA[2 * ABUF + base + 1] = hi; sA[3 * ABUF + base + 1] = lo;
    }
    __syncthreads();

    int gg = lane >> 2, tg = lane & 3;
    int m0 = (wid & 3) * 16;
    int pg = wid >> 2;
    const uint4* Bf = g_Bfrag;

#pragma unroll 1
    for (int pp = 0; pp < 2; pp++) {
        int pass = 2 * pg + pp;
        float aR[4][4], aZ[4][4], aN[4][4], aH[4][4];
#pragma unroll
        for (int nt = 0; nt < 4; nt++)
#pragma unroll
            for (int q = 0; q < 4; q++) { aR[nt][q] = 0.f; aZ[nt][q] = 0.f; aN[nt][q] = 0.f; aH[nt][q] = 0.f; }

#pragma unroll
        for (int hf = 0; hf < 2; hf++) {
            int bh_ = (hf * 2) * ABUF;
            int bl_ = (hf * 2 + 1) * ABUF;
#pragma unroll 2
            for (int ks = 0; ks < 8; ks++) {
                int kw = ks * 8 + tg;
                int rr = m0 + gg;
                unsigned Ah[4], Al[4];
                Ah[0] = sA[bh_ + rr * PITCH + kw];
                Ah[1] = sA[bh_ + (rr + 8) * PITCH + kw];
                Ah[2] = sA[bh_ + rr * PITCH + kw + 4];
                Ah[3] = sA[bh_ + (rr + 8) * PITCH + kw + 4];
                Al[0] = sA[bl_ + rr * PITCH + kw];
                Al[1] = sA[bl_ + (rr + 8) * PITCH + kw];
                Al[2] = sA[bl_ + rr * PITCH + kw + 4];
                Al[3] = sA[bl_ + (rr + 8) * PITCH + kw + 4];
                const uint4* bp = Bf + hf * 3 * 4096 + pass * 1024 + ks * 32 + lane;
#pragma unroll
                for (int nh = 0; nh < 2; nh++) {
                    uint4 b00 = bp[0 * 4096 + (2 * nh + 0) * 256];
                    uint4 b01 = bp[1 * 4096 + (2 * nh + 0) * 256];
                    uint4 b02 = bp[2 * 4096 + (2 * nh + 0) * 256];
                    uint4 b10 = bp[0 * 4096 + (2 * nh + 1) * 256];
                    uint4 b11 = bp[1 * 4096 + (2 * nh + 1) * 256];
                    uint4 b12 = bp[2 * 4096 + (2 * nh + 1) * 256];
                    float (*AN_)[4] = hf ? aH : aN;
                    int t0 = 2 * nh, t1 = 2 * nh + 1;
                    mma16816(aR[t0], Ah, b00.x, b00.y);
                    mma16816(aZ[t0], Ah, b01.x, b01.y);
                    mma16816(AN_[t0], Ah, b02.x, b02.y);
                    mma16816(aR[t1], Ah, b10.x, b10.y);
                    mma16816(aZ[t1], Ah, b11.x, b11.y);
                    mma16816(AN_[t1], Ah, b12.x, b12.y);
                    mma16816(aR[t0], Ah, b00.z, b00.w);
                    mma16816(aZ[t0], Ah, b01.z, b01.w);
                    mma16816(AN_[t0], Ah, b02.z, b02.w);
                    mma16816(aR[t1], Ah, b10.z, b10.w);
                    mma16816(aZ[t1], Ah, b11.z, b11.w);
                    mma16816(AN_[t1], Ah, b12.z, b12.w);
                    mma16816(aR[t0], Al, b00.x, b00.y);
                    mma16816(aZ[t0], Al, b01.x, b01.y);
                    mma16816(AN_[t0], Al, b02.x, b02.y);
                    mma16816(aR[t1], Al, b10.x, b10.y);
                    mma16816(aZ[t1], Al, b11.x, b11.y);
                    mma16816(AN_[t1], Al, b12.x, b12.y);
                }
            }
        }

#pragma unroll
        for (int nt = 0; nt < 4; nt++) {
#pragma unroll
            for (int rh = 0; rh < 2; rh++) {
                int rloc = m0 + rh * 8 + gg;
                int row = n0 + rloc;
                if (row < N) {
                    int col = pass * 32 + nt * 8 + tg * 2;
                    int i0 = rh * 2;
                    float rv0 = aR[nt][i0]     + sbias[col];
                    float rv1 = aR[nt][i0 + 1] + sbias[col + 1];
                    float zv0 = aZ[nt][i0]     + sbias[128 + col];
                    float zv1 = aZ[nt][i0 + 1] + sbias[128 + col + 1];
                    float in0 = aN[nt][i0]     + sbias[256 + col];
                    float in1 = aN[nt][i0 + 1] + sbias[256 + col + 1];
                    float hn0 = aH[nt][i0]     + sbias[384 + col];
                    float hn1 = aH[nt][i0 + 1] + sbias[384 + col + 1];
                    int cw = col >> 1;
                    unsigned wh = sA[2 * ABUF + rloc * PITCH + cw];
                    unsigned wl = sA[3 * ABUF + rloc * PITCH + cw];
                    float2 fh = __bfloat1622float2(*(__nv_bfloat162*)&wh);
                    float2 fl = __bfloat1622float2(*(__nv_bfloat162*)&wl);
                    float hp0 = fh.x + fl.x, hp1 = fh.y + fl.y;
                    float rg0 = fast_sigmoid(rv0);
                    float rg1 = fast_sigmoid(rv1);
                    float zg0 = fast_sigmoid(zv0);
                    float zg1 = fast_sigmoid(zv1);
                    float ng0 = fast_tanh(fmaf(rg0, hn0, in0));
                    float ng1 = fast_tanh(fmaf(rg1, hn1, in1));
                    float o0 = fmaf(zg0, hp0 - ng0, ng0);
                    float o1 = fmaf(zg1, hp1 - ng1, ng1);
                    *(float2*)(prev_out + (size_t)row * D + col) = make_float2(o0, o1);
                }
            }
        }
    }
}

// ---------------- decode -------------------------------------------------------------
__global__ void __launch_bounds__(64) dec1_kernel(int N) {
    __shared__ float s_z[DEC_ROWS * D];
    int j = threadIdx.x;
    int n0 = blockIdx.x * DEC_ROWS;
    const float inv6 = 1.f / 6.f;
    for (int i = j; i < DEC_ROWS * D; i += 64) {
        int n = n0 + i / D;
        s_z[i] = (n < N) ? g_hsum[(size_t)n0 * D + i] * inv6 : 0.f;
    }
    __syncthreads();
    float acc[DEC_ROWS];
#pragma unroll
    for (int r = 0; r < DEC_ROWS; r++) acc[r] = 0.f;
#pragma unroll 2
    for (int k = 0; k < D; k++) {
        float w = g_WTd[k * (D / 2) + j];
#pragma unroll
        for (int r = 0; r < DEC_ROWS; r++) acc[r] = fmaf(w, s_z[r * D + k], acc[r]);
    }
    float s = 0.f, sq = 0.f;
#pragma unroll
    for (int r = 0; r < DEC_ROWS; r++) {
        int n = n0 + r;
        if (n < N) {
            g_y0[(size_t)n * (D / 2) + j] = acc[r];
            s += acc[r]; sq += acc[r] * acc[r];
        }
    }
    atomicAdd(&g_stats[2 * D + j], s);
    atomicAdd(&g_stats[2 * D + (D / 2) + j], sq);
}

__global__ void dec2_kernel(const float* __restrict__ gamma, const float* __restrict__ beta,
                            const float* __restrict__ W2, float* __restrict__ out, int N) {
    int warp = (blockIdx.x * blockDim.x + threadIdx.x) >> 5;
    int lane = threadIdx.x & 31;
    if (warp >= N) return;
    float invN = 1.f / (float)N;
    float acc = 0.f;
#pragma unroll
    for (int t = 0; t < 2; t++) {
        int jj = lane + t * 32;
        float mu = g_stats[2 * D + jj] * invN;
        float var = g_stats[2 * D + (D / 2) + jj] * invN - mu * mu;
        float rs = rsqrtf(var + 1e-5f);
        float v = (g_y0[(size_t)warp * (D / 2) + jj] - mu) * rs * gamma[jj] + beta[jj];
        v = v > 0.f ? v : 0.f;
        acc = fmaf(v, W2[jj], acc);
    }
#pragma unroll
    for (int o = 16; o > 0; o >>= 1) acc += __shfl_down_sync(0xffffffffu, acc, o);
    if (lane == 0) out[warp] = acc;
}

// ---------------- launch ----------------------------------------------------------------
extern "C" void kernel_launch(void* const* d_in, const int* in_sizes, int n_in,
                              void* d_out, int out_size) {
    const float* x    = (const float*)d_in[0];
    const int*   ei   = (const int*)d_in[1];
    const float* norm = (const float*)d_in[2];
    const float* Wenc = (const float*)d_in[3];
    const float* beg  = (const float*)d_in[4];
    const float* beb  = (const float*)d_in[5];
    const float* Wih  = (const float*)d_in[6];
    const float* Whh  = (const float*)d_in[7];
    const float* bih  = (const float*)d_in[8];
    const float* bhh  = (const float*)d_in[9];
    const float* Wdec = (const float*)d_in[10];
    const float* bdg  = (const float*)d_in[11];
    const float* bdb  = (const float*)d_in[12];
    const float* W2   = (const float*)d_in[13];

    int N = in_sizes[0] / 3;
    int E = in_sizes[2];
    float* out = (float*)d_out;

    cudaFuncSetAttribute(layer_kernel, cudaFuncAttributeMaxDynamicSharedMemorySize, GRU_SMEM);

    prep_kernel<<<192, 256>>>(Wih, Whh, bih, bhh, Wdec, N);
    count_kernel<<<(E + 255) / 256, 256>>>(ei, E);
    scan_kernel<<<1, 1024>>>(N);
    fill_kernel<<<(E + 255) / 256, 256>>>(ei, norm, E);

    int nb256 = (N + 255) / 256;
    enc_stats_kernel<<<nb256, 128>>>(x, Wenc, N);
    enc_apply_kernel<<<nb256, 128>>>(x, Wenc, beg, beb, N);

    // resolve device-global addresses for ping-pong (host-side, graph-capturable)
    float* pA = nullptr;
    float* pB = nullptr;
    cudaGetSymbolAddress((void**)&pA, g_prevA);
    cudaGetSymbolAddress((void**)&pB, g_prevB);

    int gb = (N + GROWS - 1) / GROWS;
    for (int L = 0; L < 5; L++) {
        const float* pin  = (L & 1) ? pB : pA;
        float*       pout = (L & 1) ? pA : pB;
        layer_kernel<<<gb, 256, GRU_SMEM>>>(pin, pout, N);
    }

    dec1_kernel<<<(N + DEC_ROWS - 1) / DEC_ROWS, 64>>>(N);

    long long d2threads = (long long)N * 32;
    dec2_kernel<<<(int)((d2threads + 255) / 256), 256>>>(bdg, bdb, W2, out, N);
}

// round 11
// speedup vs baseline: 2.8654x; 1.1387x over previous
#include <cuda_runtime.h>
#include <cuda_fp16.h>
#include <math.h>

#define D 128
#define NMAX 50000
#define EMAX 640000
#define DEC_ROWS 32

// ---------------- scratch globals ------------------------------------------------
__device__ __align__(16) float g_prevA[NMAX * D];
__device__ __align__(16) float g_prevB[NMAX * D];
__device__ __align__(16) float g_hsum[NMAX * D];
__device__ __align__(16) float g_y0[NMAX * (D / 2)];
__device__ __align__(16) float g_stats[2 * D + 2 * (D / 2)];
__device__ __align__(16) float g_WTd[D * (D / 2)];
__device__ __align__(16) float g_bias[512];
// B fragments (single fp16): [mat(6: hf*3+gate)][ntile(16)][kstep(8)][lane(32)] -> uint2 {b0,b1}
__device__ __align__(16) uint2 g_Bfrag[6 * 4096];
// CSR-by-dst
__device__ __align__(16) int  g_deg[NMAX];
__device__ __align__(16) int  g_off[NMAX + 1];
__device__ __align__(16) int  g_pos[NMAX];
__device__ __align__(16) uint2 g_edge[EMAX];   // {src, norm_bits}

__device__ __forceinline__ unsigned pack_hi_lo_f16(float x0, float x1, unsigned& lop) {
    __half h0 = __float2half_rn(x0), h1 = __float2half_rn(x1);
    float l0 = x0 - __half2float(h0), l1 = x1 - __half2float(h1);
    __half g0 = __float2half_rn(l0), g1 = __float2half_rn(l1);
    lop = ((unsigned)__half_as_ushort(g1) << 16) | __half_as_ushort(g0);
    return ((unsigned)__half_as_ushort(h1) << 16) | __half_as_ushort(h0);
}

__device__ __forceinline__ void mma16816(float* c, const unsigned* a, unsigned b0, unsigned b1) {
    asm("mma.sync.aligned.m16n8k16.row.col.f32.f16.f16.f32 "
        "{%0,%1,%2,%3}, {%4,%5,%6,%7}, {%8,%9}, {%0,%1,%2,%3};"
        : "+f"(c[0]), "+f"(c[1]), "+f"(c[2]), "+f"(c[3])
        : "r"(a[0]), "r"(a[1]), "r"(a[2]), "r"(a[3]), "r"(b0), "r"(b1));
}

__device__ __forceinline__ float fast_sigmoid(float x) {
    return __fdividef(1.f, 1.f + __expf(-x));
}
__device__ __forceinline__ float fast_tanh(float x) {
    float e = __expf(2.f * x);
    return 1.f - __fdividef(2.f, e + 1.f);
}

// ---------------- prep ------------------------------------------------------------
__global__ void prep_kernel(const float* __restrict__ Wih, const float* __restrict__ Whh,
                            const float* __restrict__ bih, const float* __restrict__ bhh,
                            const float* __restrict__ Wdec, int N) {
    int i = blockIdx.x * blockDim.x + threadIdx.x;
    int stride = gridDim.x * blockDim.x;
    if (i < 384) g_stats[i] = 0.f;
    if (i < 256) g_bias[i] = bih[i] + bhh[i];
    else if (i < 384) g_bias[i] = bih[i];
    if (i >= 384 && i < 512) g_bias[i] = bhh[i - 128];
    for (int idx = i; idx < N; idx += stride) g_deg[idx] = 0;
    for (int idx = i; idx < D * (D / 2); idx += stride) {
        int k = idx / (D / 2), j = idx % (D / 2);
        g_WTd[idx] = Wdec[j * D + k];
    }
    for (int f = i; f < 6 * 4096; f += stride) {
        int lane = f & 31;
        int ks = (f >> 5) & 7;
        int nt = (f >> 8) & 15;
        int mat = f >> 12;
        int hf = mat / 3, gate = mat % 3;
        int gg = lane >> 2, tg = lane & 3;
        int n_local = nt * 8 + gg;
        int k0 = ks * 16 + tg * 2;
        const float* W = hf ? Whh : Wih;
        const float* row = W + (size_t)(gate * 128 + n_local) * D;
        __half a0 = __float2half_rn(row[k0]);
        __half a1 = __float2half_rn(row[k0 + 1]);
        __half a2 = __float2half_rn(row[k0 + 8]);
        __half a3 = __float2half_rn(row[k0 + 9]);
        unsigned w0 = ((unsigned)__half_as_ushort(a1) << 16) | __half_as_ushort(a0);
        unsigned w1 = ((unsigned)__half_as_ushort(a3) << 16) | __half_as_ushort(a2);
        g_Bfrag[f] = make_uint2(w0, w1);
    }
}

// ---------------- CSR build --------------------------------------------------------
__global__ void count_kernel(const int* __restrict__ ei, int E) {
    int i = blockIdx.x * blockDim.x + threadIdx.x;
    if (i < E) atomicAdd(&g_deg[ei[E + i]], 1);
}

__global__ void __launch_bounds__(1024) scan_kernel(int N) {
    __shared__ int s[1024];
    int tid = threadIdx.x;
    int chunk = (N + 1023) / 1024;
    int start = tid * chunk;
    int end = min(start + chunk, N);
    int sum = 0;
    for (int i = start; i < end; i++) sum += g_deg[i];
    s[tid] = sum;
    __syncthreads();
    for (int off = 1; off < 1024; off <<= 1) {
        int v = (tid >= off) ? s[tid - off] : 0;
        __syncthreads();
        s[tid] += v;
        __syncthreads();
    }
    int run = (tid == 0) ? 0 : s[tid - 1];
    for (int i = start; i < end; i++) {
        g_off[i] = run;
        g_pos[i] = run;
        run += g_deg[i];
    }
    if (end == N && start <= N) g_off[N] = run;
}

__global__ void fill_kernel(const int* __restrict__ ei, const float* __restrict__ norm, int E) {
    int i = blockIdx.x * blockDim.x + threadIdx.x;
    if (i < E) {
        int t = ei[E + i];
        int p = atomicAdd(&g_pos[t], 1);
        g_edge[p] = make_uint2((unsigned)ei[i], __float_as_uint(norm[i]));
    }
}

// ---------------- encoder ----------------------------------------------------------
__global__ void enc_stats_kernel(const float* __restrict__ x, const float* __restrict__ Wenc, int N) {
    int d = threadIdx.x;
    float w0 = Wenc[d * 3], w1 = Wenc[d * 3 + 1], w2 = Wenc[d * 3 + 2];
    int n0 = blockIdx.x * 256, lim = min(256, N - n0);
    float s = 0.f, sq = 0.f;
    for (int r = 0; r < lim; r++) {
        int n = n0 + r;
        float h = fmaf(x[n * 3], w0, fmaf(x[n * 3 + 1], w1, x[n * 3 + 2] * w2));
        s += h; sq += h * h;
    }
    atomicAdd(&g_stats[d], s);
    atomicAdd(&g_stats[D + d], sq);
}
__global__ void enc_apply_kernel(const float* __restrict__ x, const float* __restrict__ Wenc,
                                 const float* __restrict__ gamma, const float* __restrict__ beta, int N) {
    int d = threadIdx.x;
    float w0 = Wenc[d * 3], w1 = Wenc[d * 3 + 1], w2 = Wenc[d * 3 + 2];
    float invN = 1.f / (float)N;
    float mu = g_stats[d] * invN;
    float var = g_stats[D + d] * invN - mu * mu;
    float rs = rsqrtf(var + 1e-5f);
    float ga = gamma[d] * rs, be = beta[d] - mu * ga;
    int n0 = blockIdx.x * 256, lim = min(256, N - n0);
    for (int r = 0; r < lim; r++) {
        int n = n0 + r;
        float h = fmaf(x[n * 3], w0, fmaf(x[n * 3 + 1], w1, x[n * 3 + 2] * w2));
        float v = fmaf(h, ga, be);
        v = v > 0.f ? v : 0.f;
        g_prevA[(size_t)n * D + d] = v;
        g_hsum[(size_t)n * D + d] = v;
    }
}

// ---------------- fused layer: gather + GRU (fp16 2-term), double-buffered prev ------
#define PITCH 68
#define GROWS 64
#define ABUF  (GROWS * PITCH)
#define GRU_SMEM (4 * ABUF * 4 + 512 * 4)

__global__ void __launch_bounds__(256, 2) layer_kernel(const float* __restrict__ prev_in,
                                                       float* __restrict__ prev_out, int N) {
    extern __shared__ unsigned char smraw[];
    unsigned* sA = (unsigned*)smraw;
    float* sbias = (float*)(smraw + 4 * ABUF * 4);
    int tid = threadIdx.x;
    int n0 = blockIdx.x * GROWS;
    int lane = tid & 31, wid = tid >> 5;

#pragma unroll
    for (int t = 0; t < 2; t++) sbias[t * 256 + tid] = g_bias[t * 256 + tid];

    // --- fused gather + convert: warp w handles rows [w*8, w*8+8); reads prev_in only ---
    const float4* prev4 = (const float4*)prev_in;
#pragma unroll 1
    for (int rr = 0; rr < 8; rr++) {
        int rloc = wid * 8 + rr;
        int row = n0 + rloc;
        float4 acc = make_float4(0.f, 0.f, 0.f, 0.f);
        float4 hv = make_float4(0.f, 0.f, 0.f, 0.f);
        if (row < N) {
            int beg = g_off[row], end = g_off[row + 1];
            int j = beg;
            for (; j + 3 < end; j += 4) {
                uint2 e0 = g_edge[j], e1 = g_edge[j + 1], e2 = g_edge[j + 2], e3 = g_edge[j + 3];
                float4 v0 = prev4[(size_t)e0.x * 32 + lane];
                float4 v1 = prev4[(size_t)e1.x * 32 + lane];
                float4 v2 = prev4[(size_t)e2.x * 32 + lane];
                float4 v3 = prev4[(size_t)e3.x * 32 + lane];
                float n0v = __uint_as_float(e0.y), n1v = __uint_as_float(e1.y);
                float n2v = __uint_as_float(e2.y), n3v = __uint_as_float(e3.y);
                acc.x = fmaf(n0v, v0.x, fmaf(n1v, v1.x, fmaf(n2v, v2.x, fmaf(n3v, v3.x, acc.x))));
                acc.y = fmaf(n0v, v0.y, fmaf(n1v, v1.y, fmaf(n2v, v2.y, fmaf(n3v, v3.y, acc.y))));
                acc.z = fmaf(n0v, v0.z, fmaf(n1v, v1.z, fmaf(n2v, v2.z, fmaf(n3v, v3.z, acc.z))));
                acc.w = fmaf(n0v, v0.w, fmaf(n1v, v1.w, fmaf(n2v, v2.w, fmaf(n3v, v3.w, acc.w))));
            }
            for (; j < end; j++) {
                uint2 e0 = g_edge[j];
                float4 v0 = prev4[(size_t)e0.x * 32 + lane];
                float nv = __uint_as_float(e0.y);
                acc.x = fmaf(nv, v0.x, acc.x);
                acc.y = fmaf(nv, v0.y, acc.y);
                acc.z = fmaf(nv, v0.z, acc.z);
                acc.w = fmaf(nv, v0.w, acc.w);
            }
            hv = prev4[(size_t)row * 32 + lane];
            float4 sv = ((const float4*)g_hsum)[(size_t)row * 32 + lane];
            ((float4*)g_hsum)[(size_t)row * 32 + lane] =
                make_float4(sv.x + acc.x, sv.y + acc.y, sv.z + acc.z, sv.w + acc.w);
        }
        unsigned base = rloc * PITCH + lane * 2;
        unsigned lo, hi;
        hi = pack_hi_lo_f16(acc.x, acc.y, lo);
        sA[base] = hi; sA[ABUF + base] = lo;
        hi = pack_hi_lo_f16(acc.z, acc.w, lo);
        sA[base + 1] = hi; sA[ABUF + base + 1] = lo;
        hi = pack_hi_lo_f16(hv.x, hv.y, lo);
        sA[2 * ABUF + base] = hi; sA[3 * ABUF + base] = lo;
        hi = pack_hi_lo_f16(hv.z, hv.w, lo);
        sA[2 * ABUF + base + 1] = hi; sA[3 * ABUF + base + 1] = lo;
    }
    __syncthreads();

    int gg = lane >> 2, tg = lane & 3;
    int m0 = (wid & 3) * 16;
    int pg = wid >> 2;
    const uint2* Bf = g_Bfrag;

#pragma unroll 1
    for (int pp = 0; pp < 2; pp++) {
        int pass = 2 * pg + pp;
        float aR[4][4], aZ[4][4], aN[4][4], aH[4][4];
#pragma unroll
        for (int nt = 0; nt < 4; nt++)
#pragma unroll
            for (int q = 0; q < 4; q++) { aR[nt][q] = 0.f; aZ[nt][q] = 0.f; aN[nt][q] = 0.f; aH[nt][q] = 0.f; }

#pragma unroll
        for (int hf = 0; hf < 2; hf++) {
            int bh_ = (hf * 2) * ABUF;
            int bl_ = (hf * 2 + 1) * ABUF;
#pragma unroll 2
            for (int ks = 0; ks < 8; ks++) {
                int kw = ks * 8 + tg;
                int rr = m0 + gg;
                unsigned Ah[4], Al[4];
                Ah[0] = sA[bh_ + rr * PITCH + kw];
                Ah[1] = sA[bh_ + (rr + 8) * PITCH + kw];
                Ah[2] = sA[bh_ + rr * PITCH + kw + 4];
                Ah[3] = sA[bh_ + (rr + 8) * PITCH + kw + 4];
                Al[0] = sA[bl_ + rr * PITCH + kw];
                Al[1] = sA[bl_ + (rr + 8) * PITCH + kw];
                Al[2] = sA[bl_ + rr * PITCH + kw + 4];
                Al[3] = sA[bl_ + (rr + 8) * PITCH + kw + 4];
                const uint2* bp = Bf + hf * 3 * 4096 + pass * 1024 + ks * 32 + lane;
#pragma unroll
                for (int nh = 0; nh < 2; nh++) {
                    uint2 b00 = bp[0 * 4096 + (2 * nh + 0) * 256];
                    uint2 b01 = bp[1 * 4096 + (2 * nh + 0) * 256];
                    uint2 b02 = bp[2 * 4096 + (2 * nh + 0) * 256];
                    uint2 b10 = bp[0 * 4096 + (2 * nh + 1) * 256];
                    uint2 b11 = bp[1 * 4096 + (2 * nh + 1) * 256];
                    uint2 b12 = bp[2 * 4096 + (2 * nh + 1) * 256];
                    float (*AN_)[4] = hf ? aH : aN;
                    int t0 = 2 * nh, t1 = 2 * nh + 1;
                    // term 1: hi(A) * B   (6 independent MMAs)
                    mma16816(aR[t0], Ah, b00.x, b00.y);
                    mma16816(aZ[t0], Ah, b01.x, b01.y);
                    mma16816(AN_[t0], Ah, b02.x, b02.y);
                    mma16816(aR[t1], Ah, b10.x, b10.y);
                    mma16816(aZ[t1], Ah, b11.x, b11.y);
                    mma16816(AN_[t1], Ah, b12.x, b12.y);
                    // term 2: lo(A) * B
                    mma16816(aR[t0], Al, b00.x, b00.y);
                    mma16816(aZ[t0], Al, b01.x, b01.y);
                    mma16816(AN_[t0], Al, b02.x, b02.y);
                    mma16816(aR[t1], Al, b10.x, b10.y);
                    mma16816(aZ[t1], Al, b11.x, b11.y);
                    mma16816(AN_[t1], Al, b12.x, b12.y);
                }
            }
        }

#pragma unroll
        for (int nt = 0; nt < 4; nt++) {
#pragma unroll
            for (int rh = 0; rh < 2; rh++) {
                int rloc = m0 + rh * 8 + gg;
                int row = n0 + rloc;
                if (row < N) {
                    int col = pass * 32 + nt * 8 + tg * 2;
                    int i0 = rh * 2;
                    float rv0 = aR[nt][i0]     + sbias[col];
                    float rv1 = aR[nt][i0 + 1] + sbias[col + 1];
                    float zv0 = aZ[nt][i0]     + sbias[128 + col];
                    float zv1 = aZ[nt][i0 + 1] + sbias[128 + col + 1];
                    float in0 = aN[nt][i0]     + sbias[256 + col];
                    float in1 = aN[nt][i0 + 1] + sbias[256 + col + 1];
                    float hn0 = aH[nt][i0]     + sbias[384 + col];
                    float hn1 = aH[nt][i0 + 1] + sbias[384 + col + 1];
                    int cw = col >> 1;
                    unsigned wh = sA[2 * ABUF + rloc * PITCH + cw];
                    unsigned wl = sA[3 * ABUF + rloc * PITCH + cw];
                    float2 fh = __half22float2(*(__half2*)&wh);
                    float2 fl = __half22float2(*(__half2*)&wl);
                    float hp0 = fh.x + fl.x, hp1 = fh.y + fl.y;
                    float rg0 = fast_sigmoid(rv0);
                    float rg1 = fast_sigmoid(rv1);
                    float zg0 = fast_sigmoid(zv0);
                    float zg1 = fast_sigmoid(zv1);
                    float ng0 = fast_tanh(fmaf(rg0, hn0, in0));
                    float ng1 = fast_tanh(fmaf(rg1, hn1, in1));
                    float o0 = fmaf(zg0, hp0 - ng0, ng0);
                    float o1 = fmaf(zg1, hp1 - ng1, ng1);
                    *(float2*)(prev_out + (size_t)row * D + col) = make_float2(o0, o1);
                }
            }
        }
    }
}

// ---------------- decode -------------------------------------------------------------
__global__ void __launch_bounds__(64) dec1_kernel(int N) {
    __shared__ float s_z[DEC_ROWS * D];
    int j = threadIdx.x;
    int n0 = blockIdx.x * DEC_ROWS;
    const float inv6 = 1.f / 6.f;
    for (int i = j; i < DEC_ROWS * D; i += 64) {
        int n = n0 + i / D;
        s_z[i] = (n < N) ? g_hsum[(size_t)n0 * D + i] * inv6 : 0.f;
    }
    __syncthreads();
    float acc[DEC_ROWS];
#pragma unroll
    for (int r = 0; r < DEC_ROWS; r++) acc[r] = 0.f;
#pragma unroll 2
    for (int k = 0; k < D; k++) {
        float w = g_WTd[k * (D / 2) + j];
#pragma unroll
        for (int r = 0; r < DEC_ROWS; r++) acc[r] = fmaf(w, s_z[r * D + k], acc[r]);
    }
    float s = 0.f, sq = 0.f;
#pragma unroll
    for (int r = 0; r < DEC_ROWS; r++) {
        int n = n0 + r;
        if (n < N) {
            g_y0[(size_t)n * (D / 2) + j] = acc[r];
            s += acc[r]; sq += acc[r] * acc[r];
        }
    }
    atomicAdd(&g_stats[2 * D + j], s);
    atomicAdd(&g_stats[2 * D + (D / 2) + j], sq);
}

__global__ void dec2_kernel(const float* __restrict__ gamma, const float* __restrict__ beta,
                            const float* __restrict__ W2, float* __restrict__ out, int N) {
    int warp = (blockIdx.x * blockDim.x + threadIdx.x) >> 5;
    int lane = threadIdx.x & 31;
    if (warp >= N) return;
    float invN = 1.f / (float)N;
    float acc = 0.f;
#pragma unroll
    for (int t = 0; t < 2; t++) {
        int jj = lane + t * 32;
        float mu = g_stats[2 * D + jj] * invN;
        float var = g_stats[2 * D + (D / 2) + jj] * invN - mu * mu;
        float rs = rsqrtf(var + 1e-5f);
        float v = (g_y0[(size_t)warp * (D / 2) + jj] - mu) * rs * gamma[jj] + beta[jj];
        v = v > 0.f ? v : 0.f;
        acc = fmaf(v, W2[jj], acc);
    }
#pragma unroll
    for (int o = 16; o > 0; o >>= 1) acc += __shfl_down_sync(0xffffffffu, acc, o);
    if (lane == 0) out[warp] = acc;
}

// ---------------- launch ----------------------------------------------------------------
extern "C" void kernel_launch(void* const* d_in, const int* in_sizes, int n_in,
                              void* d_out, int out_size) {
    const float* x    = (const float*)d_in[0];
    const int*   ei   = (const int*)d_in[1];
    const float* norm = (const float*)d_in[2];
    const float* Wenc = (const float*)d_in[3];
    const float* beg  = (const float*)d_in[4];
    const float* beb  = (const float*)d_in[5];
    const float* Wih  = (const float*)d_in[6];
    const float* Whh  = (const float*)d_in[7];
    const float* bih  = (const float*)d_in[8];
    const float* bhh  = (const float*)d_in[9];
    const float* Wdec = (const float*)d_in[10];
    const float* bdg  = (const float*)d_in[11];
    const float* bdb  = (const float*)d_in[12];
    const float* W2   = (const float*)d_in[13];

    int N = in_sizes[0] / 3;
    int E = in_sizes[2];
    float* out = (float*)d_out;

    cudaFuncSetAttribute(layer_kernel, cudaFuncAttributeMaxDynamicSharedMemorySize, GRU_SMEM);

    prep_kernel<<<192, 256>>>(Wih, Whh, bih, bhh, Wdec, N);
    count_kernel<<<(E + 255) / 256, 256>>>(ei, E);
    scan_kernel<<<1, 1024>>>(N);
    fill_kernel<<<(E + 255) / 256, 256>>>(ei, norm, E);

    int nb256 = (N + 255) / 256;
    enc_stats_kernel<<<nb256, 128>>>(x, Wenc, N);
    enc_apply_kernel<<<nb256, 128>>>(x, Wenc, beg, beb, N);

    float* pA = nullptr;
    float* pB = nullptr;
    cudaGetSymbolAddress((void**)&pA, g_prevA);
    cudaGetSymbolAddress((void**)&pB, g_prevB);

    int gb = (N + GROWS - 1) / GROWS;
    for (int L = 0; L < 5; L++) {
        const float* pin  = (L & 1) ? pB : pA;
        float*       pout = (L & 1) ? pA : pB;
        layer_kernel<<<gb, 256, GRU_SMEM>>>(pin, pout, N);
    }

    dec1_kernel<<<(N + DEC_ROWS - 1) / DEC_ROWS, 64>>>(N);

    long long d2threads = (long long)N * 32;
    dec2_kernel<<<(int)((d2threads + 255) / 256), 256>>>(bdg, bdb, W2, out, N);
}